// round 11
// baseline (speedup 1.0000x reference)
#include <cuda_runtime.h>
#include <cuda_fp16.h>
#include <cuda_fp8.h>
#include <cstdint>

typedef __half h16;
typedef unsigned char u8;

#define BB 4
#define CC 512
#define HWN 4096
#define NG 32
#define CPG 16
#define QK_SCALE 0.044194173824159216f  // 1/sqrt(512)
#define PAD 40                           // fp16 smem pitch in halves (80 B rows)
#define PITCH8 80                        // fp8 smem pitch in bytes (64 B payload + 16 pad)
#define STAGES 3
#define OP_BYTES (128 * 80)              // one operand, one stage = 10240 B (same for fp16/fp8)
#define STAGE_BYTES (2 * OP_BYTES)       // A + B per stage = 20480 B
#define SMEM_TOTAL (STAGES * STAGE_BYTES)  // 61440 B

// ---------------- static scratch ----------------
__device__ float g_stats[BB * NG * 2];          // mean, inv per (b, group)
__device__ h16   g_ht[(size_t)BB * HWN * CC];   // normed H^T [b][n][c] fp16
__device__ u8    g_qt8[(size_t)BB * HWN * CC];  // Q^T [b][n][c] e4m3
__device__ u8    g_kt8[(size_t)BB * HWN * CC];  // K^T [b][m][c] e4m3
__device__ u8    g_v8 [(size_t)BB * CC * HWN];  // V   [b][c][m] e4m3
__device__ u8    g_s8 [(size_t)BB * HWN * HWN]; // exp(scores) e4m3 [b][n][m]
__device__ h16   g_ot[(size_t)BB * HWN * CC];   // (attn@V)^T [b][n][c] fp16
__device__ h16   g_wb[(size_t)4 * CC * CC];     // wq,wk,wv,wp fp16
__device__ float g_psum[(size_t)BB * HWN * 64]; // partial row sums of dequantized exp
__device__ float g_zinv[(size_t)BB * HWN];      // 1 / rowsum

// ---------------- GroupNorm stats ----------------
__global__ __launch_bounds__(256) void gn_stats_kernel(const float* __restrict__ x) {
    int b = blockIdx.x / NG, g = blockIdx.x % NG;
    const float* xp = x + ((size_t)b * CC + (size_t)g * CPG) * HWN;
    const int n = CPG * HWN;  // 65536

    float s = 0.f, s2 = 0.f;
    for (int i = threadIdx.x * 4; i < n; i += 1024) {
        float4 v = *(const float4*)&xp[i];
        s  += v.x + v.y + v.z + v.w;
        s2 += v.x * v.x + v.y * v.y + v.z * v.z + v.w * v.w;
    }
    __shared__ float rs[256], rs2[256];
    rs[threadIdx.x] = s; rs2[threadIdx.x] = s2;
    __syncthreads();
    for (int st = 128; st > 0; st >>= 1) {
        if (threadIdx.x < st) {
            rs[threadIdx.x]  += rs[threadIdx.x + st];
            rs2[threadIdx.x] += rs2[threadIdx.x + st];
        }
        __syncthreads();
    }
    if (threadIdx.x == 0) {
        float mean = rs[0] / n;
        float var  = rs2[0] / n - mean * mean;
        g_stats[blockIdx.x * 2]     = mean;
        g_stats[blockIdx.x * 2 + 1] = rsqrtf(var + 1e-6f);
    }
}

// ---------------- norm + transpose: x [c][n] fp32 -> g_ht [n][c] fp16 ----------------
__global__ __launch_bounds__(256) void trn_kernel(const float* __restrict__ x,
                                                  const float* __restrict__ gamma,
                                                  const float* __restrict__ beta) {
    __shared__ float t[32][33];
    int b = blockIdx.z;
    int n0 = blockIdx.x * 32, c0 = blockIdx.y * 32;
    const float* src = x + (size_t)b * CC * HWN;
    h16* dst = g_ht + (size_t)b * HWN * CC;
    int tx = threadIdx.x & 31, ty = threadIdx.x >> 5;
#pragma unroll
    for (int r = 0; r < 4; r++) {
        int c = c0 + ty + r * 8;
        float mean = g_stats[(b * NG + c / CPG) * 2];
        float inv  = g_stats[(b * NG + c / CPG) * 2 + 1];
        float v = src[(size_t)c * HWN + n0 + tx];
        t[ty + r * 8][tx] = (v - mean) * inv * gamma[c] + beta[c];
    }
    __syncthreads();
#pragma unroll
    for (int r = 0; r < 4; r++)
        dst[(size_t)(n0 + ty + r * 8) * CC + c0 + tx] = __float2half(t[tx][ty + r * 8]);
}

// ---------------- weight fp32 -> fp16 ----------------
__global__ __launch_bounds__(256) void wconv_kernel(const float* __restrict__ wq,
                                                    const float* __restrict__ wk,
                                                    const float* __restrict__ wv,
                                                    const float* __restrict__ wp) {
    const float* srcs[4] = {wq, wk, wv, wp};
    int m = blockIdx.y;
    int idx = blockIdx.x * 256 + threadIdx.x;
    float4 v = *(const float4*)&srcs[m][idx * 4];
    h16* dst = g_wb + (size_t)m * CC * CC + idx * 4;
    *(__half2*)&dst[0] = __floats2half2_rn(v.x, v.y);
    *(__half2*)&dst[2] = __floats2half2_rn(v.z, v.w);
}

// ---------------- Z reduce ----------------
__global__ __launch_bounds__(256) void zred_kernel() {
    int row = blockIdx.x * 256 + threadIdx.x;
    const float* p = g_psum + (size_t)row * 64;
    float s = 0.f;
#pragma unroll
    for (int i = 0; i < 16; i++) {
        float4 v = *(const float4*)&p[i * 4];
        s += v.x + v.y + v.z + v.w;
    }
    g_zinv[row] = 1.0f / s;
}

// ---------------- helpers ----------------
__device__ __forceinline__ uint32_t smem_u32(const void* p) {
    return (uint32_t)__cvta_generic_to_shared(p);
}
__device__ __forceinline__ void cp16(uint32_t d, const void* s) {
    asm volatile("cp.async.cg.shared.global [%0], [%1], 16;" :: "r"(d), "l"(s));
}
__device__ __forceinline__ void ldmx4(uint32_t addr, uint32_t& r0, uint32_t& r1,
                                      uint32_t& r2, uint32_t& r3) {
    asm volatile("ldmatrix.sync.aligned.m8n8.x4.shared.b16 {%0,%1,%2,%3}, [%4];"
                 : "=r"(r0), "=r"(r1), "=r"(r2), "=r"(r3) : "r"(addr));
}
__device__ __forceinline__ void mma16816f(float c[4], uint32_t a0, uint32_t a1, uint32_t a2,
                                          uint32_t a3, uint32_t b0, uint32_t b1) {
    asm volatile(
        "mma.sync.aligned.m16n8k16.row.col.f32.f16.f16.f32 "
        "{%0,%1,%2,%3}, {%4,%5,%6,%7}, {%8,%9}, {%0,%1,%2,%3};"
        : "+f"(c[0]), "+f"(c[1]), "+f"(c[2]), "+f"(c[3])
        : "r"(a0), "r"(a1), "r"(a2), "r"(a3), "r"(b0), "r"(b1));
}
__device__ __forceinline__ void mma16832q(float c[4], uint32_t a0, uint32_t a1, uint32_t a2,
                                          uint32_t a3, uint32_t b0, uint32_t b1) {
    asm volatile(
        "mma.sync.aligned.m16n8k32.row.col.f32.e4m3.e4m3.f32 "
        "{%0,%1,%2,%3}, {%4,%5,%6,%7}, {%8,%9}, {%0,%1,%2,%3};"
        : "+f"(c[0]), "+f"(c[1]), "+f"(c[2]), "+f"(c[3])
        : "r"(a0), "r"(a1), "r"(a2), "r"(a3), "r"(b0), "r"(b1));
}
__device__ __forceinline__ u8 f2e4m3(float v) {
    return (u8)__nv_cvt_float_to_fp8(v, __NV_SATFINITE, __NV_E4M3);
}
__device__ __forceinline__ unsigned short f2x2e4m3(float a, float b) {
    return (unsigned short)__nv_cvt_float2_to_fp8x2(make_float2(a, b), __NV_SATFINITE, __NV_E4M3);
}
__device__ __forceinline__ float2 e4m3x2f(unsigned short q) {
    __half2_raw hr = __nv_cvt_fp8x2_to_halfraw2((__nv_fp8x2_storage_t)q, __NV_E4M3);
    return __half22float2(*(__half2*)&hr);
}

// ================= fp16 GEMM core (R6/R10-validated shape) =================
// C[i 128][j 128] = sum_k A[i][k] B[j][k], fp16 operands, fp32 accum.
// EPI 3: fp32 + bias + residual
// EPI 6: e4m3 transposed via smem, +bias
// EPI 7: e4m3 direct, +bias
template <int EPI>
__device__ __forceinline__ void gemm_core(unsigned char* sm,
                                          const h16* __restrict__ A, int lda,
                                          const h16* __restrict__ B, int ldb, int K,
                                          void* Cg, int ldc,
                                          const float* __restrict__ bias,
                                          const float* __restrict__ resid,
                                          int i0, int j0) {
    int tid = threadIdx.x, lane = tid & 31, wid = tid >> 5;
    int wm = wid >> 1, wn = wid & 1;

    float accf[2][8][4];
#pragma unroll
    for (int mi = 0; mi < 2; mi++)
#pragma unroll
        for (int ni = 0; ni < 8; ni++)
#pragma unroll
            for (int r = 0; r < 4; r++) accf[mi][ni][r] = 0.f;

    int lr = tid >> 2, lc = (tid & 3) * 8;
    const h16* Ag  = A + (size_t)(i0 + lr) * lda + lc;
    const h16* Ag2 = Ag + (size_t)64 * lda;
    const h16* Bg  = B + (size_t)(j0 + lr) * ldb + lc;
    const h16* Bg2 = Bg + (size_t)64 * ldb;

    uint32_t smBase = smem_u32(sm);
    uint32_t wOff = smBase + (lr * PAD + lc) * 2;

    int am_row = wm * 32 + (lane & 15);
    int a_kh   = (lane >> 4) * 8;
    uint32_t aAddr = smBase + (am_row * PAD + a_kh) * 2;
    int b_nl  = (lane & 7) + ((lane >> 4) << 3);
    int b_sel = ((lane >> 3) & 1) * 8;
    uint32_t bAddr = smBase + OP_BYTES + ((wn * 64 + b_nl) * PAD + b_sel) * 2;

    const int nK = K / 32;

#pragma unroll
    for (int s = 0; s < STAGES - 1; s++) {
        uint32_t d = wOff + s * STAGE_BYTES;
        cp16(d,                           Ag  + s * 32);
        cp16(d + 64 * PAD * 2,            Ag2 + s * 32);
        cp16(d + OP_BYTES,                Bg  + s * 32);
        cp16(d + OP_BYTES + 64 * PAD * 2, Bg2 + s * 32);
        asm volatile("cp.async.commit_group;");
    }

    for (int kt = 0; kt < nK; kt++) {
        asm volatile("cp.async.wait_group 1;" ::: "memory");
        __syncthreads();

        int pf = kt + STAGES - 1;
        if (pf < nK) {
            uint32_t d = wOff + (pf % STAGES) * STAGE_BYTES;
            cp16(d,                           Ag  + pf * 32);
            cp16(d + 64 * PAD * 2,            Ag2 + pf * 32);
            cp16(d + OP_BYTES,                Bg  + pf * 32);
            cp16(d + OP_BYTES + 64 * PAD * 2, Bg2 + pf * 32);
        }
        asm volatile("cp.async.commit_group;");

        uint32_t stOff = (kt % STAGES) * STAGE_BYTES;
#pragma unroll
        for (int ks = 0; ks < 32; ks += 16) {
            uint32_t af[2][4];
#pragma unroll
            for (int mi = 0; mi < 2; mi++)
                ldmx4(aAddr + stOff + (mi * 16 * PAD + ks) * 2,
                      af[mi][0], af[mi][1], af[mi][2], af[mi][3]);
            uint32_t bf4[4][4];
#pragma unroll
            for (int nq = 0; nq < 4; nq++)
                ldmx4(bAddr + stOff + (nq * 16 * PAD + ks) * 2,
                      bf4[nq][0], bf4[nq][1], bf4[nq][2], bf4[nq][3]);
#pragma unroll
            for (int mi = 0; mi < 2; mi++)
#pragma unroll
                for (int ni = 0; ni < 8; ni++)
                    mma16816f(accf[mi][ni], af[mi][0], af[mi][1], af[mi][2], af[mi][3],
                              bf4[ni >> 1][(ni & 1) * 2], bf4[ni >> 1][(ni & 1) * 2 + 1]);
        }
    }

    int g = lane >> 2, t = lane & 3;

    if (EPI == 6) {  // e4m3 transposed via smem (+bias on i-dim)
        __syncthreads();
        u8* Ct = (u8*)sm;  // [j 128][pitch 144 bytes]
#pragma unroll
        for (int mi = 0; mi < 2; mi++) {
            int r = wm * 32 + mi * 16 + g;
            float bv0 = bias ? bias[i0 + r] : 0.f;
            float bv8 = bias ? bias[i0 + r + 8] : 0.f;
#pragma unroll
            for (int ni = 0; ni < 8; ni++) {
                int c = wn * 64 + ni * 8 + 2 * t;
                Ct[(size_t)c * 144 + r]           = f2e4m3(accf[mi][ni][0] + bv0);
                Ct[(size_t)(c + 1) * 144 + r]     = f2e4m3(accf[mi][ni][1] + bv0);
                Ct[(size_t)c * 144 + r + 8]       = f2e4m3(accf[mi][ni][2] + bv8);
                Ct[(size_t)(c + 1) * 144 + r + 8] = f2e4m3(accf[mi][ni][3] + bv8);
            }
        }
        __syncthreads();
        int j = tid >> 1, h2 = tid & 1;
        u8* Crow = (u8*)Cg + (size_t)(j0 + j) * ldc + i0 + h2 * 64;
        const u8* Srow = Ct + (size_t)j * 144 + h2 * 64;
#pragma unroll
        for (int q = 0; q < 4; q++)
            *(uint4*)(Crow + q * 16) = *(const uint4*)(Srow + q * 16);
    } else if (EPI == 7) {  // e4m3 direct + bias
        u8* C = (u8*)Cg;
#pragma unroll
        for (int mi = 0; mi < 2; mi++) {
            int r0 = wm * 32 + mi * 16 + g;
            float bv0 = bias ? bias[i0 + r0] : 0.f;
            float bv8 = bias ? bias[i0 + r0 + 8] : 0.f;
#pragma unroll
            for (int ni = 0; ni < 8; ni++) {
                int col = j0 + wn * 64 + ni * 8 + 2 * t;
                *(unsigned short*)&C[(size_t)(i0 + r0) * ldc + col] =
                    f2x2e4m3(accf[mi][ni][0] + bv0, accf[mi][ni][1] + bv0);
                *(unsigned short*)&C[(size_t)(i0 + r0 + 8) * ldc + col] =
                    f2x2e4m3(accf[mi][ni][2] + bv8, accf[mi][ni][3] + bv8);
            }
        }
    } else {  // EPI 3: fp32 + bias + residual
        float* C = (float*)Cg;
#pragma unroll
        for (int mi = 0; mi < 2; mi++) {
            int r0 = wm * 32 + mi * 16 + g;
            float bv0 = bias[i0 + r0];
            float bv8 = bias[i0 + r0 + 8];
#pragma unroll
            for (int ni = 0; ni < 8; ni++) {
                int col = j0 + wn * 64 + ni * 8 + 2 * t;
                size_t o0 = (size_t)(i0 + r0) * ldc + col;
                size_t o8 = (size_t)(i0 + r0 + 8) * ldc + col;
                float2 x0 = *(const float2*)&resid[o0];
                float2 x8 = *(const float2*)&resid[o8];
                *(float2*)&C[o0] = make_float2(accf[mi][ni][0] + bv0 + x0.x,
                                               accf[mi][ni][1] + bv0 + x0.y);
                *(float2*)&C[o8] = make_float2(accf[mi][ni][2] + bv8 + x8.x,
                                               accf[mi][ni][3] + bv8 + x8.y);
            }
        }
    }
}

// ================= fp8 GEMM core =================
// C[i 128][j 128] = sum_k A[i][k] B[j][k], e4m3 operands, fp32 accum.
// Same 80-byte pitch / byte geometry as fp16 core; KC = 64 elements/chunk.
// SEPI 0: exp(acc*scale) -> e4m3 out + psum of dequantized values
// SEPI 1: fp16 transposed via smem, column-scaled by zinv[j]
template <int SEPI>
__device__ __forceinline__ void gemm_core8(unsigned char* sm,
                                           const u8* __restrict__ A, int lda,
                                           const u8* __restrict__ B, int ldb, int K,
                                           void* Cg, int ldc,
                                           float scale,
                                           float* __restrict__ psum,
                                           const float* __restrict__ zinv,
                                           int i0, int j0) {
    int tid = threadIdx.x, lane = tid & 31, wid = tid >> 5;
    int wm = wid >> 1, wn = wid & 1;

    float accf[2][8][4];
#pragma unroll
    for (int mi = 0; mi < 2; mi++)
#pragma unroll
        for (int ni = 0; ni < 8; ni++)
#pragma unroll
            for (int r = 0; r < 4; r++) accf[mi][ni][r] = 0.f;

    int lr = tid >> 1, lc = (tid & 1) * 32;  // row 0..127, byte col 0/32
    const u8* Ag = A + (size_t)(i0 + lr) * lda + lc;
    const u8* Bg = B + (size_t)(j0 + lr) * ldb + lc;

    uint32_t smBase = smem_u32(sm);
    uint32_t wOffA = smBase + lr * PITCH8 + lc;
    uint32_t wOffB = smBase + OP_BYTES + lr * PITCH8 + lc;

    int am_row = wm * 32 + (lane & 15);
    int a_kh   = (lane >> 4) * 16;            // byte offset
    uint32_t aAddr = smBase + am_row * PITCH8 + a_kh;
    int b_nl  = (lane & 7) + ((lane >> 4) << 3);
    int b_sel = ((lane >> 3) & 1) * 16;       // byte offset
    uint32_t bAddr = smBase + OP_BYTES + (wn * 64 + b_nl) * PITCH8 + b_sel;

    const int nK = K / 64;

#pragma unroll
    for (int s = 0; s < STAGES - 1; s++) {
        uint32_t dA = wOffA + s * STAGE_BYTES;
        uint32_t dB = wOffB + s * STAGE_BYTES;
        cp16(dA,      Ag + s * 64);
        cp16(dA + 16, Ag + s * 64 + 16);
        cp16(dB,      Bg + s * 64);
        cp16(dB + 16, Bg + s * 64 + 16);
        asm volatile("cp.async.commit_group;");
    }

    for (int kt = 0; kt < nK; kt++) {
        asm volatile("cp.async.wait_group 1;" ::: "memory");
        __syncthreads();

        int pf = kt + STAGES - 1;
        if (pf < nK) {
            uint32_t dA = wOffA + (pf % STAGES) * STAGE_BYTES;
            uint32_t dB = wOffB + (pf % STAGES) * STAGE_BYTES;
            cp16(dA,      Ag + pf * 64);
            cp16(dA + 16, Ag + pf * 64 + 16);
            cp16(dB,      Bg + pf * 64);
            cp16(dB + 16, Bg + pf * 64 + 16);
        }
        asm volatile("cp.async.commit_group;");

        uint32_t stOff = (kt % STAGES) * STAGE_BYTES;
#pragma unroll
        for (int ks = 0; ks < 64; ks += 32) {  // bytes, one k32 mma step each
            uint32_t af[2][4];
#pragma unroll
            for (int mi = 0; mi < 2; mi++)
                ldmx4(aAddr + stOff + mi * 16 * PITCH8 + ks,
                      af[mi][0], af[mi][1], af[mi][2], af[mi][3]);
            uint32_t bf4[4][4];
#pragma unroll
            for (int nq = 0; nq < 4; nq++)
                ldmx4(bAddr + stOff + nq * 16 * PITCH8 + ks,
                      bf4[nq][0], bf4[nq][1], bf4[nq][2], bf4[nq][3]);
#pragma unroll
            for (int mi = 0; mi < 2; mi++)
#pragma unroll
                for (int ni = 0; ni < 8; ni++)
                    mma16832q(accf[mi][ni], af[mi][0], af[mi][1], af[mi][2], af[mi][3],
                              bf4[ni >> 1][(ni & 1) * 2], bf4[ni >> 1][(ni & 1) * 2 + 1]);
        }
    }

    int g = lane >> 2, t = lane & 3;

    if (SEPI == 0) {  // exp -> e4m3 + psum (dequantized for exact Z)
        u8* C = (u8*)Cg;
        int slot = (j0 >> 7) * 2 + wn;
#pragma unroll
        for (int mi = 0; mi < 2; mi++) {
            int r0 = wm * 32 + mi * 16 + g;
            float s0 = 0.f, s8 = 0.f;
#pragma unroll
            for (int ni = 0; ni < 8; ni++) {
                int col = j0 + wn * 64 + ni * 8 + 2 * t;
                float p0 = __expf(accf[mi][ni][0] * scale);
                float p1 = __expf(accf[mi][ni][1] * scale);
                float p2 = __expf(accf[mi][ni][2] * scale);
                float p3 = __expf(accf[mi][ni][3] * scale);
                unsigned short q01 = f2x2e4m3(p0, p1);
                unsigned short q23 = f2x2e4m3(p2, p3);
                float2 d01 = e4m3x2f(q01);
                float2 d23 = e4m3x2f(q23);
                s0 += d01.x + d01.y;
                s8 += d23.x + d23.y;
                *(unsigned short*)&C[(size_t)(i0 + r0) * ldc + col]     = q01;
                *(unsigned short*)&C[(size_t)(i0 + r0 + 8) * ldc + col] = q23;
            }
            s0 += __shfl_xor_sync(0xffffffffu, s0, 1);
            s0 += __shfl_xor_sync(0xffffffffu, s0, 2);
            s8 += __shfl_xor_sync(0xffffffffu, s8, 1);
            s8 += __shfl_xor_sync(0xffffffffu, s8, 2);
            if (t == 0) {
                psum[(size_t)(i0 + r0) * 64 + slot]     = s0;
                psum[(size_t)(i0 + r0 + 8) * 64 + slot] = s8;
            }
        }
    } else {  // SEPI 1: fp16 transposed, col-scaled by zinv[j]
        __syncthreads();
        h16* Ct = (h16*)sm;  // [j 128][i pitch 136 halves]
#pragma unroll
        for (int mi = 0; mi < 2; mi++) {
            int r = wm * 32 + mi * 16 + g;
#pragma unroll
            for (int ni = 0; ni < 8; ni++) {
                int c = wn * 64 + ni * 8 + 2 * t;
                float z0 = zinv[j0 + c];
                float z1 = zinv[j0 + c + 1];
                Ct[(size_t)c * 136 + r]           = __float2half(accf[mi][ni][0] * z0);
                Ct[(size_t)(c + 1) * 136 + r]     = __float2half(accf[mi][ni][1] * z1);
                Ct[(size_t)c * 136 + r + 8]       = __float2half(accf[mi][ni][2] * z0);
                Ct[(size_t)(c + 1) * 136 + r + 8] = __float2half(accf[mi][ni][3] * z1);
            }
        }
        __syncthreads();
        int j = tid >> 1, h2 = tid & 1;
        h16* Crow = (h16*)Cg + (size_t)(j0 + j) * ldc + i0 + h2 * 64;
        const h16* Srow = Ct + (size_t)j * 136 + h2 * 64;
#pragma unroll
        for (int q = 0; q < 8; q++)
            *(uint4*)(Crow + q * 8) = *(const uint4*)(Srow + q * 8);
    }
}

// ---------------- GEMM wrappers (dynamic smem) ----------------
extern __shared__ unsigned char dyn_sm[];

__global__ __launch_bounds__(256, 2) void gemm_qkv_kernel(const float* __restrict__ bq,
                                                          const float* __restrict__ bk,
                                                          const float* __restrict__ bv) {
    int z = blockIdx.z, b = z / 3, m = z % 3;
    const h16* A = g_wb + (size_t)m * CC * CC;
    const h16* B = g_ht + (size_t)b * HWN * CC;
    int i0 = blockIdx.y * 128, j0 = blockIdx.x * 128;
    if (m == 0)
        gemm_core<6>(dyn_sm, A, CC, B, CC, CC, g_qt8 + (size_t)b * HWN * CC, CC,
                     bq, nullptr, i0, j0);
    else if (m == 1)
        gemm_core<6>(dyn_sm, A, CC, B, CC, CC, g_kt8 + (size_t)b * HWN * CC, CC,
                     bk, nullptr, i0, j0);
    else
        gemm_core<7>(dyn_sm, A, CC, B, CC, CC, g_v8 + (size_t)b * CC * HWN, HWN,
                     bv, nullptr, i0, j0);
}

__global__ __launch_bounds__(256, 2) void gemm_scores_kernel() {
    int b = blockIdx.z;
    int i0 = blockIdx.y * 128, j0 = blockIdx.x * 128;
    gemm_core8<0>(dyn_sm, g_qt8 + (size_t)b * HWN * CC, CC,
                  g_kt8 + (size_t)b * HWN * CC, CC, CC,
                  g_s8 + (size_t)b * HWN * HWN, HWN, QK_SCALE,
                  g_psum + (size_t)b * HWN * 64, nullptr, i0, j0);
}

__global__ __launch_bounds__(256, 2) void gemm_av_kernel() {
    int b = blockIdx.z;
    int i0 = blockIdx.y * 128, j0 = blockIdx.x * 128;  // i over c, j over n
    gemm_core8<1>(dyn_sm, g_v8 + (size_t)b * CC * HWN, HWN,
                  g_s8 + (size_t)b * HWN * HWN, HWN, HWN,
                  g_ot + (size_t)b * HWN * CC, CC, 1.f,
                  nullptr, g_zinv + (size_t)b * HWN, i0, j0);
}

__global__ __launch_bounds__(256, 2) void gemm_proj_kernel(const float* __restrict__ bp,
                                                           const float* __restrict__ x,
                                                           float* __restrict__ out) {
    int b = blockIdx.z;
    int i0 = blockIdx.y * 128, j0 = blockIdx.x * 128;  // i over o(c), j over n
    gemm_core<3>(dyn_sm, g_wb + (size_t)3 * CC * CC, CC,
                 g_ot + (size_t)b * HWN * CC, CC, CC,
                 out + (size_t)b * CC * HWN, HWN, bp, x + (size_t)b * CC * HWN, i0, j0);
}

// ---------------- launch ----------------
extern "C" void kernel_launch(void* const* d_in, const int* in_sizes, int n_in,
                              void* d_out, int out_size) {
    const float* x     = (const float*)d_in[0];
    const float* gamma = (const float*)d_in[1];
    const float* beta  = (const float*)d_in[2];
    const float* wq = (const float*)d_in[3]; const float* bq = (const float*)d_in[4];
    const float* wk = (const float*)d_in[5]; const float* bk = (const float*)d_in[6];
    const float* wv = (const float*)d_in[7]; const float* bv = (const float*)d_in[8];
    const float* wp = (const float*)d_in[9]; const float* bp = (const float*)d_in[10];
    float* out = (float*)d_out;

    cudaFuncSetAttribute(gemm_qkv_kernel,    cudaFuncAttributeMaxDynamicSharedMemorySize, SMEM_TOTAL);
    cudaFuncSetAttribute(gemm_scores_kernel, cudaFuncAttributeMaxDynamicSharedMemorySize, SMEM_TOTAL);
    cudaFuncSetAttribute(gemm_av_kernel,     cudaFuncAttributeMaxDynamicSharedMemorySize, SMEM_TOTAL);
    cudaFuncSetAttribute(gemm_proj_kernel,   cudaFuncAttributeMaxDynamicSharedMemorySize, SMEM_TOTAL);

    gn_stats_kernel<<<BB * NG, 256>>>(x);
    trn_kernel<<<dim3(HWN / 32, CC / 32, BB), 256>>>(x, gamma, beta);
    wconv_kernel<<<dim3(CC * CC / 4 / 256, 4), 256>>>(wq, wk, wv, wp);
    gemm_qkv_kernel<<<dim3(HWN / 128, CC / 128, BB * 3), 256, SMEM_TOTAL>>>(bq, bk, bv);
    gemm_scores_kernel<<<dim3(HWN / 128, HWN / 128, BB), 256, SMEM_TOTAL>>>();
    zred_kernel<<<BB * HWN / 256, 256>>>();
    gemm_av_kernel<<<dim3(HWN / 128, CC / 128, BB), 256, SMEM_TOTAL>>>();
    gemm_proj_kernel<<<dim3(HWN / 128, CC / 128, BB), 256, SMEM_TOTAL>>>(bp, x, out);
}

// round 12
// speedup vs baseline: 1.0442x; 1.0442x over previous
#include <cuda_runtime.h>
#include <cuda_fp16.h>
#include <cstdint>

typedef __half h16;

#define BB 4
#define CC 512
#define HWN 4096
#define NG 32
#define CPG 16
#define QK_SCALE 0.044194173824159216f  // 1/sqrt(512)
#define PAD 40                           // smem pitch (halves) for 32-wide K tiles
#define STAGES 3
#define OP_BYTES (128 * PAD * 2)         // one operand, one stage = 10240 B
#define STAGE_BYTES (2 * OP_BYTES)       // A + B per stage = 20480 B
#define SMEM_TOTAL (STAGES * STAGE_BYTES)  // 61440 B
// wide scores kernel: A 128 rows, B 256 rows, pitch 40 halves
#define S_OPA 10240
#define S_STAGE 30720
#define S_SMEM (STAGES * S_STAGE)        // 92160 B

// ---------------- static scratch ----------------
__device__ float g_stats[BB * NG * 2];          // mean, inv per (b, group)
__device__ h16   g_ht[(size_t)BB * HWN * CC];   // normed H^T [b][n][c]
__device__ h16   g_qt[(size_t)BB * HWN * CC];   // Q^T [b][n][c]
__device__ h16   g_kt[(size_t)BB * HWN * CC];   // K^T [b][m][c]
__device__ h16   g_v [(size_t)BB * CC * HWN];   // V   [b][c][m]
__device__ h16   g_sb[(size_t)BB * HWN * HWN];  // exp(scores) fp16 [b][n][m]
__device__ h16   g_ot[(size_t)BB * HWN * CC];   // (attn@V)^T [b][n][c]
__device__ h16   g_wb[(size_t)4 * CC * CC];     // wq,wk,wv,wp fp16
__device__ float g_psum[(size_t)BB * HWN * 64]; // partial row sums of exp(scores)
__device__ float g_zinv[(size_t)BB * HWN];      // 1 / rowsum

// ---------------- GroupNorm stats ----------------
__global__ __launch_bounds__(256) void gn_stats_kernel(const float* __restrict__ x) {
    int b = blockIdx.x / NG, g = blockIdx.x % NG;
    const float* xp = x + ((size_t)b * CC + (size_t)g * CPG) * HWN;
    const int n = CPG * HWN;  // 65536

    float s = 0.f, s2 = 0.f;
    for (int i = threadIdx.x * 4; i < n; i += 1024) {
        float4 v = *(const float4*)&xp[i];
        s  += v.x + v.y + v.z + v.w;
        s2 += v.x * v.x + v.y * v.y + v.z * v.z + v.w * v.w;
    }
    __shared__ float rs[256], rs2[256];
    rs[threadIdx.x] = s; rs2[threadIdx.x] = s2;
    __syncthreads();
    for (int st = 128; st > 0; st >>= 1) {
        if (threadIdx.x < st) {
            rs[threadIdx.x]  += rs[threadIdx.x + st];
            rs2[threadIdx.x] += rs2[threadIdx.x + st];
        }
        __syncthreads();
    }
    if (threadIdx.x == 0) {
        float mean = rs[0] / n;
        float var  = rs2[0] / n - mean * mean;
        g_stats[blockIdx.x * 2]     = mean;
        g_stats[blockIdx.x * 2 + 1] = rsqrtf(var + 1e-6f);
    }
}

// ---------------- norm + transpose: x [c][n] fp32 -> g_ht [n][c] fp16 ----------------
__global__ __launch_bounds__(256) void trn_kernel(const float* __restrict__ x,
                                                  const float* __restrict__ gamma,
                                                  const float* __restrict__ beta) {
    __shared__ float t[32][33];
    int b = blockIdx.z;
    int n0 = blockIdx.x * 32, c0 = blockIdx.y * 32;
    const float* src = x + (size_t)b * CC * HWN;
    h16* dst = g_ht + (size_t)b * HWN * CC;
    int tx = threadIdx.x & 31, ty = threadIdx.x >> 5;
#pragma unroll
    for (int r = 0; r < 4; r++) {
        int c = c0 + ty + r * 8;
        float mean = g_stats[(b * NG + c / CPG) * 2];
        float inv  = g_stats[(b * NG + c / CPG) * 2 + 1];
        float v = src[(size_t)c * HWN + n0 + tx];
        t[ty + r * 8][tx] = (v - mean) * inv * gamma[c] + beta[c];
    }
    __syncthreads();
#pragma unroll
    for (int r = 0; r < 4; r++)
        dst[(size_t)(n0 + ty + r * 8) * CC + c0 + tx] = __float2half(t[tx][ty + r * 8]);
}

// ---------------- weight fp32 -> fp16 ----------------
__global__ __launch_bounds__(256) void wconv_kernel(const float* __restrict__ wq,
                                                    const float* __restrict__ wk,
                                                    const float* __restrict__ wv,
                                                    const float* __restrict__ wp) {
    const float* srcs[4] = {wq, wk, wv, wp};
    int m = blockIdx.y;
    int idx = blockIdx.x * 256 + threadIdx.x;
    float4 v = *(const float4*)&srcs[m][idx * 4];
    h16* dst = g_wb + (size_t)m * CC * CC + idx * 4;
    *(__half2*)&dst[0] = __floats2half2_rn(v.x, v.y);
    *(__half2*)&dst[2] = __floats2half2_rn(v.z, v.w);
}

// ---------------- Z reduce: g_psum[row][64] -> g_zinv[row] ----------------
__global__ __launch_bounds__(256) void zred_kernel() {
    int row = blockIdx.x * 256 + threadIdx.x;
    const float* p = g_psum + (size_t)row * 64;
    float s = 0.f;
#pragma unroll
    for (int i = 0; i < 16; i++) {
        float4 v = *(const float4*)&p[i * 4];
        s += v.x + v.y + v.z + v.w;
    }
    g_zinv[row] = 1.0f / s;
}

// ---------------- mma helpers ----------------
__device__ __forceinline__ uint32_t smem_u32(const void* p) {
    return (uint32_t)__cvta_generic_to_shared(p);
}
__device__ __forceinline__ void cp16(uint32_t d, const void* s) {
    asm volatile("cp.async.cg.shared.global [%0], [%1], 16;" :: "r"(d), "l"(s));
}
__device__ __forceinline__ void ldmx4(uint32_t addr, uint32_t& r0, uint32_t& r1,
                                      uint32_t& r2, uint32_t& r3) {
    asm volatile("ldmatrix.sync.aligned.m8n8.x4.shared.b16 {%0,%1,%2,%3}, [%4];"
                 : "=r"(r0), "=r"(r1), "=r"(r2), "=r"(r3) : "r"(addr));
}
__device__ __forceinline__ void mma16816f(float c[4], uint32_t a0, uint32_t a1, uint32_t a2,
                                          uint32_t a3, uint32_t b0, uint32_t b1) {
    asm volatile(
        "mma.sync.aligned.m16n8k16.row.col.f32.f16.f16.f32 "
        "{%0,%1,%2,%3}, {%4,%5,%6,%7}, {%8,%9}, {%0,%1,%2,%3};"
        : "+f"(c[0]), "+f"(c[1]), "+f"(c[2]), "+f"(c[3])
        : "r"(a0), "r"(a1), "r"(a2), "r"(a3), "r"(b0), "r"(b1));
}
__device__ __forceinline__ void mma16816h(uint32_t c[2], uint32_t a0, uint32_t a1, uint32_t a2,
                                          uint32_t a3, uint32_t b0, uint32_t b1) {
    asm volatile(
        "mma.sync.aligned.m16n8k16.row.col.f16.f16.f16.f16 "
        "{%0,%1}, {%2,%3,%4,%5}, {%6,%7}, {%0,%1};"
        : "+r"(c[0]), "+r"(c[1])
        : "r"(a0), "r"(a1), "r"(a2), "r"(a3), "r"(b0), "r"(b1));
}

// ---------------- GEMM core (R6/R10 shape): C[i 128][j 128] ----------------
// EPI 0: f16 direct, +bias   EPI 2: f16 transposed, +bias   EPI 3: fp32+bias+resid
// EPI 5: f16 transposed, col-scaled by zinv
template <int EPI>
__device__ __forceinline__ void gemm_core(unsigned char* sm,
                                          const h16* __restrict__ A, int lda,
                                          const h16* __restrict__ B, int ldb, int K,
                                          void* Cg, int ldc,
                                          const float* __restrict__ bias,
                                          const float* __restrict__ resid,
                                          const float* __restrict__ zinv,
                                          int i0, int j0) {
    int tid = threadIdx.x, lane = tid & 31, wid = tid >> 5;
    int wm = wid >> 1, wn = wid & 1;

    float accf[2][8][4];
#pragma unroll
    for (int mi = 0; mi < 2; mi++)
#pragma unroll
        for (int ni = 0; ni < 8; ni++)
#pragma unroll
            for (int r = 0; r < 4; r++) accf[mi][ni][r] = 0.f;

    int lr = tid >> 2, lc = (tid & 3) * 8;
    const h16* Ag  = A + (size_t)(i0 + lr) * lda + lc;
    const h16* Ag2 = Ag + (size_t)64 * lda;
    const h16* Bg  = B + (size_t)(j0 + lr) * ldb + lc;
    const h16* Bg2 = Bg + (size_t)64 * ldb;

    uint32_t smBase = smem_u32(sm);
    uint32_t wOff = smBase + (lr * PAD + lc) * 2;

    int am_row = wm * 32 + (lane & 15);
    int a_kh   = (lane >> 4) * 8;
    uint32_t aAddr = smBase + (am_row * PAD + a_kh) * 2;
    int b_nl  = (lane & 7) + ((lane >> 4) << 3);
    int b_sel = ((lane >> 3) & 1) * 8;
    uint32_t bAddr = smBase + OP_BYTES + ((wn * 64 + b_nl) * PAD + b_sel) * 2;

    const int nK = K / 32;

#pragma unroll
    for (int s = 0; s < STAGES - 1; s++) {
        uint32_t d = wOff + s * STAGE_BYTES;
        cp16(d,                           Ag  + s * 32);
        cp16(d + 64 * PAD * 2,            Ag2 + s * 32);
        cp16(d + OP_BYTES,                Bg  + s * 32);
        cp16(d + OP_BYTES + 64 * PAD * 2, Bg2 + s * 32);
        asm volatile("cp.async.commit_group;");
    }

    for (int kt = 0; kt < nK; kt++) {
        asm volatile("cp.async.wait_group 1;" ::: "memory");
        __syncthreads();

        int pf = kt + STAGES - 1;
        if (pf < nK) {
            uint32_t d = wOff + (pf % STAGES) * STAGE_BYTES;
            cp16(d,                           Ag  + pf * 32);
            cp16(d + 64 * PAD * 2,            Ag2 + pf * 32);
            cp16(d + OP_BYTES,                Bg  + pf * 32);
            cp16(d + OP_BYTES + 64 * PAD * 2, Bg2 + pf * 32);
        }
        asm volatile("cp.async.commit_group;");

        uint32_t stOff = (kt % STAGES) * STAGE_BYTES;
#pragma unroll
        for (int ks = 0; ks < 32; ks += 16) {
            uint32_t af[2][4];
#pragma unroll
            for (int mi = 0; mi < 2; mi++)
                ldmx4(aAddr + stOff + (mi * 16 * PAD + ks) * 2,
                      af[mi][0], af[mi][1], af[mi][2], af[mi][3]);
            uint32_t bf4[4][4];
#pragma unroll
            for (int nq = 0; nq < 4; nq++)
                ldmx4(bAddr + stOff + (nq * 16 * PAD + ks) * 2,
                      bf4[nq][0], bf4[nq][1], bf4[nq][2], bf4[nq][3]);
#pragma unroll
            for (int mi = 0; mi < 2; mi++)
#pragma unroll
                for (int ni = 0; ni < 8; ni++)
                    mma16816f(accf[mi][ni], af[mi][0], af[mi][1], af[mi][2], af[mi][3],
                              bf4[ni >> 1][(ni & 1) * 2], bf4[ni >> 1][(ni & 1) * 2 + 1]);
        }
    }

    int g = lane >> 2, t = lane & 3;

    if (EPI == 0) {  // f16 direct + bias
        h16* C = (h16*)Cg;
#pragma unroll
        for (int mi = 0; mi < 2; mi++) {
            int r0 = wm * 32 + mi * 16 + g;
            float bv0 = bias ? bias[i0 + r0] : 0.f;
            float bv8 = bias ? bias[i0 + r0 + 8] : 0.f;
#pragma unroll
            for (int ni = 0; ni < 8; ni++) {
                int col = j0 + wn * 64 + ni * 8 + 2 * t;
                *(__half2*)&C[(size_t)(i0 + r0) * ldc + col] =
                    __floats2half2_rn(accf[mi][ni][0] + bv0, accf[mi][ni][1] + bv0);
                *(__half2*)&C[(size_t)(i0 + r0 + 8) * ldc + col] =
                    __floats2half2_rn(accf[mi][ni][2] + bv8, accf[mi][ni][3] + bv8);
            }
        }
    } else if (EPI == 2 || EPI == 5) {  // f16 transposed via smem
        __syncthreads();
        h16* Ct = (h16*)sm;  // [j 128][i pitch 136]
#pragma unroll
        for (int mi = 0; mi < 2; mi++) {
            int r = wm * 32 + mi * 16 + g;
            float bv0 = (EPI == 2 && bias) ? bias[i0 + r] : 0.f;
            float bv8 = (EPI == 2 && bias) ? bias[i0 + r + 8] : 0.f;
#pragma unroll
            for (int ni = 0; ni < 8; ni++) {
                int c = wn * 64 + ni * 8 + 2 * t;
                float z0 = 1.f, z1 = 1.f;
                if (EPI == 5) {
                    z0 = zinv[j0 + c];
                    z1 = zinv[j0 + c + 1];
                }
                Ct[(size_t)c * 136 + r]           = __float2half(accf[mi][ni][0] * z0 + bv0);
                Ct[(size_t)(c + 1) * 136 + r]     = __float2half(accf[mi][ni][1] * z1 + bv0);
                Ct[(size_t)c * 136 + r + 8]       = __float2half(accf[mi][ni][2] * z0 + bv8);
                Ct[(size_t)(c + 1) * 136 + r + 8] = __float2half(accf[mi][ni][3] * z1 + bv8);
            }
        }
        __syncthreads();
        int j = tid >> 1, h = tid & 1;
        h16* Crow = (h16*)Cg + (size_t)(j0 + j) * ldc + i0 + h * 64;
        const h16* Srow = Ct + (size_t)j * 136 + h * 64;
#pragma unroll
        for (int q = 0; q < 8; q++)
            *(uint4*)(Crow + q * 8) = *(const uint4*)(Srow + q * 8);
    } else {  // EPI 3: fp32 + bias + residual
        float* C = (float*)Cg;
#pragma unroll
        for (int mi = 0; mi < 2; mi++) {
            int r0 = wm * 32 + mi * 16 + g;
            float bv0 = bias[i0 + r0];
            float bv8 = bias[i0 + r0 + 8];
#pragma unroll
            for (int ni = 0; ni < 8; ni++) {
                int col = j0 + wn * 64 + ni * 8 + 2 * t;
                size_t o0 = (size_t)(i0 + r0) * ldc + col;
                size_t o8 = (size_t)(i0 + r0 + 8) * ldc + col;
                float2 x0 = *(const float2*)&resid[o0];
                float2 x8 = *(const float2*)&resid[o8];
                *(float2*)&C[o0] = make_float2(accf[mi][ni][0] + bv0 + x0.x,
                                               accf[mi][ni][1] + bv0 + x0.y);
                *(float2*)&C[o8] = make_float2(accf[mi][ni][2] + bv8 + x8.x,
                                               accf[mi][ni][3] + bv8 + x8.y);
            }
        }
    }
}

// ---------------- GEMM wrappers (dynamic smem) ----------------
extern __shared__ unsigned char dyn_sm[];

__global__ __launch_bounds__(256, 2) void gemm_qkv_kernel(const float* __restrict__ bq,
                                                          const float* __restrict__ bk,
                                                          const float* __restrict__ bv) {
    int z = blockIdx.z, b = z / 3, m = z % 3;
    const h16* A = g_wb + (size_t)m * CC * CC;
    const h16* B = g_ht + (size_t)b * HWN * CC;
    int i0 = blockIdx.y * 128, j0 = blockIdx.x * 128;
    if (m == 0)
        gemm_core<2>(dyn_sm, A, CC, B, CC, CC, g_qt + (size_t)b * HWN * CC, CC,
                     bq, nullptr, nullptr, i0, j0);
    else if (m == 1)
        gemm_core<2>(dyn_sm, A, CC, B, CC, CC, g_kt + (size_t)b * HWN * CC, CC,
                     bk, nullptr, nullptr, i0, j0);
    else
        gemm_core<0>(dyn_sm, A, CC, B, CC, CC, g_v + (size_t)b * CC * HWN, HWN,
                     bv, nullptr, nullptr, i0, j0);
}

// ---------------- wide scores kernel: C[i 128][j 256], 64x64 warp tiles, f16 acc ------
__global__ __launch_bounds__(256, 2) void gemm_scores_kernel() {
    int b = blockIdx.z;
    const h16* A = g_qt + (size_t)b * HWN * CC;  // rows i = n
    const h16* B = g_kt + (size_t)b * HWN * CC;  // rows j = m
    h16* C = g_sb + (size_t)b * HWN * HWN;
    float* psum = g_psum + (size_t)b * HWN * 64;
    int i0 = blockIdx.y * 128, j0 = blockIdx.x * 256;

    int tid = threadIdx.x, lane = tid & 31, wid = tid >> 5;
    int wm = wid >> 2, wn = wid & 3;  // 2 x 4 layout, 64x64 per warp

    uint32_t acch[4][8][2];
#pragma unroll
    for (int mi = 0; mi < 4; mi++)
#pragma unroll
        for (int ni = 0; ni < 8; ni++) { acch[mi][ni][0] = 0u; acch[mi][ni][1] = 0u; }

    // copy slots: A 2 per thread (512 x 16B), B 4 per thread (1024 x 16B)
    int aq = tid * 2, ar = aq >> 2, akb = aq & 3;      // two consecutive kb slots
    int bq = tid * 4, br = bq >> 2;                    // four kb slots = full row chunk
    const h16* Ag = A + (size_t)(i0 + ar) * CC + akb * 8;
    const h16* Bg = B + (size_t)(j0 + br) * CC;

    uint32_t smBase = smem_u32(dyn_sm);
    uint32_t aOff = smBase + (ar * PAD + akb * 8) * 2;
    uint32_t bOff = smBase + S_OPA + (br * PAD) * 2;

    int am_row = wm * 64 + (lane & 15);
    int a_kh   = (lane >> 4) * 8;
    uint32_t aAddr = smBase + (am_row * PAD + a_kh) * 2;
    int b_nl  = (lane & 7) + ((lane >> 4) << 3);
    int b_sel = ((lane >> 3) & 1) * 8;
    uint32_t bAddr = smBase + S_OPA + ((wn * 64 + b_nl) * PAD + b_sel) * 2;

    const int nK = CC / 32;  // 16

#pragma unroll
    for (int s = 0; s < STAGES - 1; s++) {
        uint32_t da = aOff + s * S_STAGE;
        uint32_t db = bOff + s * S_STAGE;
        cp16(da,      Ag + s * 32);
        cp16(da + 16, Ag + s * 32 + 8);
        cp16(db,      Bg + s * 32);
        cp16(db + 16, Bg + s * 32 + 8);
        cp16(db + 32, Bg + s * 32 + 16);
        cp16(db + 48, Bg + s * 32 + 24);
        asm volatile("cp.async.commit_group;");
    }

    for (int kt = 0; kt < nK; kt++) {
        asm volatile("cp.async.wait_group 1;" ::: "memory");
        __syncthreads();

        int pf = kt + STAGES - 1;
        if (pf < nK) {
            uint32_t da = aOff + (pf % STAGES) * S_STAGE;
            uint32_t db = bOff + (pf % STAGES) * S_STAGE;
            cp16(da,      Ag + pf * 32);
            cp16(da + 16, Ag + pf * 32 + 8);
            cp16(db,      Bg + pf * 32);
            cp16(db + 16, Bg + pf * 32 + 8);
            cp16(db + 32, Bg + pf * 32 + 16);
            cp16(db + 48, Bg + pf * 32 + 24);
        }
        asm volatile("cp.async.commit_group;");

        uint32_t stOff = (kt % STAGES) * S_STAGE;
#pragma unroll
        for (int ks = 0; ks < 32; ks += 16) {
            uint32_t af[4][4];
#pragma unroll
            for (int mi = 0; mi < 4; mi++)
                ldmx4(aAddr + stOff + (mi * 16 * PAD + ks) * 2,
                      af[mi][0], af[mi][1], af[mi][2], af[mi][3]);
            uint32_t bf4[4][4];
#pragma unroll
            for (int nq = 0; nq < 4; nq++)
                ldmx4(bAddr + stOff + (nq * 16 * PAD + ks) * 2,
                      bf4[nq][0], bf4[nq][1], bf4[nq][2], bf4[nq][3]);
#pragma unroll
            for (int mi = 0; mi < 4; mi++)
#pragma unroll
                for (int ni = 0; ni < 8; ni++)
                    mma16816h(acch[mi][ni], af[mi][0], af[mi][1], af[mi][2], af[mi][3],
                              bf4[ni >> 1][(ni & 1) * 2], bf4[ni >> 1][(ni & 1) * 2 + 1]);
        }
    }

    int g = lane >> 2, t = lane & 3;
    int slot = (j0 >> 6) + wn;
#pragma unroll
    for (int mi = 0; mi < 4; mi++) {
        int r0 = wm * 64 + mi * 16 + g;
        float s0 = 0.f, s8 = 0.f;
#pragma unroll
        for (int ni = 0; ni < 8; ni++) {
            int col = j0 + wn * 64 + ni * 8 + 2 * t;
            float2 lo = __half22float2(*(const __half2*)&acch[mi][ni][0]);
            float2 hi = __half22float2(*(const __half2*)&acch[mi][ni][1]);
            float p0 = __expf(lo.x * QK_SCALE);
            float p1 = __expf(lo.y * QK_SCALE);
            float p2 = __expf(hi.x * QK_SCALE);
            float p3 = __expf(hi.y * QK_SCALE);
            s0 += p0 + p1;
            s8 += p2 + p3;
            *(__half2*)&C[(size_t)(i0 + r0) * HWN + col]     = __floats2half2_rn(p0, p1);
            *(__half2*)&C[(size_t)(i0 + r0 + 8) * HWN + col] = __floats2half2_rn(p2, p3);
        }
        s0 += __shfl_xor_sync(0xffffffffu, s0, 1);
        s0 += __shfl_xor_sync(0xffffffffu, s0, 2);
        s8 += __shfl_xor_sync(0xffffffffu, s8, 1);
        s8 += __shfl_xor_sync(0xffffffffu, s8, 2);
        if (t == 0) {
            psum[(size_t)(i0 + r0) * 64 + slot]     = s0;
            psum[(size_t)(i0 + r0 + 8) * 64 + slot] = s8;
        }
    }
}

__global__ __launch_bounds__(256, 2) void gemm_av_kernel() {
    int b = blockIdx.z;
    int i0 = blockIdx.y * 128, j0 = blockIdx.x * 128;  // i over c, j over n
    gemm_core<5>(dyn_sm, g_v + (size_t)b * CC * HWN, HWN,
                 g_sb + (size_t)b * HWN * HWN, HWN, HWN,
                 g_ot + (size_t)b * HWN * CC, CC, nullptr, nullptr,
                 g_zinv + (size_t)b * HWN, i0, j0);
}

__global__ __launch_bounds__(256, 2) void gemm_proj_kernel(const float* __restrict__ bp,
                                                           const float* __restrict__ x,
                                                           float* __restrict__ out) {
    int b = blockIdx.z;
    int i0 = blockIdx.y * 128, j0 = blockIdx.x * 128;  // i over o(c), j over n
    gemm_core<3>(dyn_sm, g_wb + (size_t)3 * CC * CC, CC,
                 g_ot + (size_t)b * HWN * CC, CC, CC,
                 out + (size_t)b * CC * HWN, HWN, bp, x + (size_t)b * CC * HWN,
                 nullptr, i0, j0);
}

// ---------------- launch ----------------
extern "C" void kernel_launch(void* const* d_in, const int* in_sizes, int n_in,
                              void* d_out, int out_size) {
    const float* x     = (const float*)d_in[0];
    const float* gamma = (const float*)d_in[1];
    const float* beta  = (const float*)d_in[2];
    const float* wq = (const float*)d_in[3]; const float* bq = (const float*)d_in[4];
    const float* wk = (const float*)d_in[5]; const float* bk = (const float*)d_in[6];
    const float* wv = (const float*)d_in[7]; const float* bv = (const float*)d_in[8];
    const float* wp = (const float*)d_in[9]; const float* bp = (const float*)d_in[10];
    float* out = (float*)d_out;

    cudaFuncSetAttribute(gemm_qkv_kernel,    cudaFuncAttributeMaxDynamicSharedMemorySize, SMEM_TOTAL);
    cudaFuncSetAttribute(gemm_scores_kernel, cudaFuncAttributeMaxDynamicSharedMemorySize, S_SMEM);
    cudaFuncSetAttribute(gemm_av_kernel,     cudaFuncAttributeMaxDynamicSharedMemorySize, SMEM_TOTAL);
    cudaFuncSetAttribute(gemm_proj_kernel,   cudaFuncAttributeMaxDynamicSharedMemorySize, SMEM_TOTAL);

    gn_stats_kernel<<<BB * NG, 256>>>(x);
    trn_kernel<<<dim3(HWN / 32, CC / 32, BB), 256>>>(x, gamma, beta);
    wconv_kernel<<<dim3(CC * CC / 4 / 256, 4), 256>>>(wq, wk, wv, wp);
    gemm_qkv_kernel<<<dim3(HWN / 128, CC / 128, BB * 3), 256, SMEM_TOTAL>>>(bq, bk, bv);
    gemm_scores_kernel<<<dim3(HWN / 256, HWN / 128, BB), 256, S_SMEM>>>();
    zred_kernel<<<BB * HWN / 256, 256>>>();
    gemm_av_kernel<<<dim3(HWN / 128, CC / 128, BB), 256, SMEM_TOTAL>>>();
    gemm_proj_kernel<<<dim3(HWN / 128, CC / 128, BB), 256, SMEM_TOTAL>>>(bp, x, out);
}

// round 13
// speedup vs baseline: 1.1714x; 1.1218x over previous
#include <cuda_runtime.h>
#include <cuda_fp16.h>
#include <cstdint>

typedef __half h16;

#define BB 4
#define CC 512
#define HWN 4096
#define NG 32
#define CPG 16
#define QK_SCALE 0.044194173824159216f  // 1/sqrt(512)
#define PAD 40                           // smem pitch (halves) for 32-wide K tiles
#define STAGES 3
#define OP_BYTES (128 * PAD * 2)         // one operand, one stage = 10240 B
#define STAGE_BYTES (2 * OP_BYTES)       // A + B per stage = 20480 B
#define SMEM_TOTAL (STAGES * STAGE_BYTES)  // 61440 B

// ---------------- static scratch ----------------
__device__ h16   g_ht[(size_t)BB * HWN * CC];   // normed H^T [b][n][c]
__device__ h16   g_qt[(size_t)BB * HWN * CC];   // Q^T [b][n][c]
__device__ h16   g_kt[(size_t)BB * HWN * CC];   // K^T [b][m][c]
__device__ h16   g_v [(size_t)BB * CC * HWN];   // V   [b][c][m]
__device__ h16   g_sb[(size_t)BB * HWN * HWN];  // exp(scores) fp16 [b][n][m]
__device__ h16   g_ot[(size_t)BB * HWN * CC];   // (attn@V)^T [b][n][c]
__device__ h16   g_wb[(size_t)4 * CC * CC];     // wq,wk,wv,wp fp16
__device__ float g_psum[(size_t)BB * HWN * 64]; // partial row sums of exp(scores)
__device__ float g_zinv[(size_t)BB * HWN];      // 1 / rowsum

// ---------------- fused GroupNorm + transpose ----------------
// One block per (b, group). Pass 1: stats over the 16x4096 slice.
// Pass 2: re-read (L2-hot), normalize, write transposed fp16 to g_ht[n][c].
__global__ __launch_bounds__(256) void gnt_kernel(const float* __restrict__ x,
                                                  const float* __restrict__ gamma,
                                                  const float* __restrict__ beta) {
    int b = blockIdx.x / NG, g = blockIdx.x % NG;
    const float* xp = x + ((size_t)b * CC + (size_t)g * CPG) * HWN;
    const int n = CPG * HWN;  // 65536
    int tid = threadIdx.x;

    // ---- pass 1: stats ----
    float s = 0.f, s2 = 0.f;
    for (int i = tid * 4; i < n; i += 1024) {
        float4 v = *(const float4*)&xp[i];
        s  += v.x + v.y + v.z + v.w;
        s2 += v.x * v.x + v.y * v.y + v.z * v.z + v.w * v.w;
    }
    __shared__ float rs[256], rs2[256];
    rs[tid] = s; rs2[tid] = s2;
    __syncthreads();
    for (int st = 128; st > 0; st >>= 1) {
        if (tid < st) {
            rs[tid]  += rs[tid + st];
            rs2[tid] += rs2[tid + st];
        }
        __syncthreads();
    }
    float mean = rs[0] / n;
    float var  = rs2[0] / n - mean * mean;
    float inv  = rsqrtf(var + 1e-6f);

    // per-channel affine: out = v * A[c] + B2[c]
    __shared__ float Ac[CPG], Bc[CPG];
    if (tid < CPG) {
        float ga = gamma[g * CPG + tid];
        Ac[tid] = ga * inv;
        Bc[tid] = beta[g * CPG + tid] - mean * ga * inv;
    }
    __syncthreads();

    // ---- pass 2: normalize + transpose, 16c x 256n tiles ----
    __shared__ float tile[CPG][256];
    h16* dst = g_ht + (size_t)b * HWN * CC + g * CPG;
    int n4 = (tid & 63) * 4, r0 = tid >> 6;  // r0 in 0..3
    for (int n0 = 0; n0 < HWN; n0 += 256) {
#pragma unroll
        for (int r = r0; r < CPG; r += 4)
            *(float4*)&tile[r][n4] = *(const float4*)&xp[(size_t)r * HWN + n0 + n4];
        __syncthreads();
        {
            int nn = tid;  // 0..255
            uint4 pk[2];
            h16* ph = (h16*)pk;
#pragma unroll
            for (int c = 0; c < CPG; c++)
                ph[c] = __float2half(tile[c][nn] * Ac[c] + Bc[c]);
            h16* drow = dst + (size_t)(n0 + nn) * CC;
            *(uint4*)&drow[0] = pk[0];
            *(uint4*)&drow[8] = pk[1];
        }
        __syncthreads();
    }
}

// ---------------- weight fp32 -> fp16 ----------------
__global__ __launch_bounds__(256) void wconv_kernel(const float* __restrict__ wq,
                                                    const float* __restrict__ wk,
                                                    const float* __restrict__ wv,
                                                    const float* __restrict__ wp) {
    const float* srcs[4] = {wq, wk, wv, wp};
    int m = blockIdx.y;
    int idx = blockIdx.x * 256 + threadIdx.x;
    float4 v = *(const float4*)&srcs[m][idx * 4];
    h16* dst = g_wb + (size_t)m * CC * CC + idx * 4;
    *(__half2*)&dst[0] = __floats2half2_rn(v.x, v.y);
    *(__half2*)&dst[2] = __floats2half2_rn(v.z, v.w);
}

// ---------------- Z reduce: g_psum[row][64] -> g_zinv[row] ----------------
__global__ __launch_bounds__(256) void zred_kernel() {
    int row = blockIdx.x * 256 + threadIdx.x;
    const float* p = g_psum + (size_t)row * 64;
    float s = 0.f;
#pragma unroll
    for (int i = 0; i < 16; i++) {
        float4 v = *(const float4*)&p[i * 4];
        s += v.x + v.y + v.z + v.w;
    }
    g_zinv[row] = 1.0f / s;
}

// ---------------- mma helpers ----------------
__device__ __forceinline__ uint32_t smem_u32(const void* p) {
    return (uint32_t)__cvta_generic_to_shared(p);
}
__device__ __forceinline__ void cp16(uint32_t d, const void* s) {
    asm volatile("cp.async.cg.shared.global [%0], [%1], 16;" :: "r"(d), "l"(s));
}
__device__ __forceinline__ void ldmx4(uint32_t addr, uint32_t& r0, uint32_t& r1,
                                      uint32_t& r2, uint32_t& r3) {
    asm volatile("ldmatrix.sync.aligned.m8n8.x4.shared.b16 {%0,%1,%2,%3}, [%4];"
                 : "=r"(r0), "=r"(r1), "=r"(r2), "=r"(r3) : "r"(addr));
}
__device__ __forceinline__ void mma16816f(float c[4], uint32_t a0, uint32_t a1, uint32_t a2,
                                          uint32_t a3, uint32_t b0, uint32_t b1) {
    asm volatile(
        "mma.sync.aligned.m16n8k16.row.col.f32.f16.f16.f32 "
        "{%0,%1,%2,%3}, {%4,%5,%6,%7}, {%8,%9}, {%0,%1,%2,%3};"
        : "+f"(c[0]), "+f"(c[1]), "+f"(c[2]), "+f"(c[3])
        : "r"(a0), "r"(a1), "r"(a2), "r"(a3), "r"(b0), "r"(b1));
}
__device__ __forceinline__ void mma16816h(uint32_t c[2], uint32_t a0, uint32_t a1, uint32_t a2,
                                          uint32_t a3, uint32_t b0, uint32_t b1) {
    asm volatile(
        "mma.sync.aligned.m16n8k16.row.col.f16.f16.f16.f16 "
        "{%0,%1}, {%2,%3,%4,%5}, {%6,%7}, {%0,%1};"
        : "+r"(c[0]), "+r"(c[1])
        : "r"(a0), "r"(a1), "r"(a2), "r"(a3), "r"(b0), "r"(b1));
}

// ---------------- GEMM core: C[i 128][j 128] = sum_k A[i][k] B[j][k] ----------------
// 3-stage cp.async pipeline (R6/R10-validated shape). fp16 operands.
// HACC=1: fp16 accumulators (scores only).
// EPI 0: f16 direct, +bias   EPI 2: f16 transposed, +bias   EPI 3: fp32+bias+resid
// EPI 4: f16 exp(acc*scale) + psum   EPI 5: f16 transposed, col-scaled by zinv
template <int EPI, int HACC>
__device__ __forceinline__ void gemm_core(unsigned char* sm,
                                          const h16* __restrict__ A, int lda,
                                          const h16* __restrict__ B, int ldb, int K,
                                          void* Cg, int ldc,
                                          const float* __restrict__ bias, float scale,
                                          const float* __restrict__ resid,
                                          float* __restrict__ psum,
                                          const float* __restrict__ zinv,
                                          int i0, int j0) {
    int tid = threadIdx.x, lane = tid & 31, wid = tid >> 5;
    int wm = wid >> 1, wn = wid & 1;

    float    accf[2][8][4];
    uint32_t acch[2][8][2];
    if (HACC) {
#pragma unroll
        for (int mi = 0; mi < 2; mi++)
#pragma unroll
            for (int ni = 0; ni < 8; ni++) { acch[mi][ni][0] = 0u; acch[mi][ni][1] = 0u; }
    } else {
#pragma unroll
        for (int mi = 0; mi < 2; mi++)
#pragma unroll
            for (int ni = 0; ni < 8; ni++)
#pragma unroll
                for (int r = 0; r < 4; r++) accf[mi][ni][r] = 0.f;
    }

    int lr = tid >> 2, lc = (tid & 3) * 8;
    const h16* Ag  = A + (size_t)(i0 + lr) * lda + lc;
    const h16* Ag2 = Ag + (size_t)64 * lda;
    const h16* Bg  = B + (size_t)(j0 + lr) * ldb + lc;
    const h16* Bg2 = Bg + (size_t)64 * ldb;

    uint32_t smBase = smem_u32(sm);
    uint32_t wOff = smBase + (lr * PAD + lc) * 2;

    int am_row = wm * 32 + (lane & 15);
    int a_kh   = (lane >> 4) * 8;
    uint32_t aAddr = smBase + (am_row * PAD + a_kh) * 2;
    int b_nl  = (lane & 7) + ((lane >> 4) << 3);
    int b_sel = ((lane >> 3) & 1) * 8;
    uint32_t bAddr = smBase + OP_BYTES + ((wn * 64 + b_nl) * PAD + b_sel) * 2;

    const int nK = K / 32;

#pragma unroll
    for (int s = 0; s < STAGES - 1; s++) {
        uint32_t d = wOff + s * STAGE_BYTES;
        cp16(d,                           Ag  + s * 32);
        cp16(d + 64 * PAD * 2,            Ag2 + s * 32);
        cp16(d + OP_BYTES,                Bg  + s * 32);
        cp16(d + OP_BYTES + 64 * PAD * 2, Bg2 + s * 32);
        asm volatile("cp.async.commit_group;");
    }

    for (int kt = 0; kt < nK; kt++) {
        asm volatile("cp.async.wait_group 1;" ::: "memory");
        __syncthreads();

        int pf = kt + STAGES - 1;
        if (pf < nK) {
            uint32_t d = wOff + (pf % STAGES) * STAGE_BYTES;
            cp16(d,                           Ag  + pf * 32);
            cp16(d + 64 * PAD * 2,            Ag2 + pf * 32);
            cp16(d + OP_BYTES,                Bg  + pf * 32);
            cp16(d + OP_BYTES + 64 * PAD * 2, Bg2 + pf * 32);
        }
        asm volatile("cp.async.commit_group;");

        uint32_t stOff = (kt % STAGES) * STAGE_BYTES;
#pragma unroll
        for (int ks = 0; ks < 32; ks += 16) {
            uint32_t af[2][4];
#pragma unroll
            for (int mi = 0; mi < 2; mi++)
                ldmx4(aAddr + stOff + (mi * 16 * PAD + ks) * 2,
                      af[mi][0], af[mi][1], af[mi][2], af[mi][3]);
            uint32_t bf4[4][4];
#pragma unroll
            for (int nq = 0; nq < 4; nq++)
                ldmx4(bAddr + stOff + (nq * 16 * PAD + ks) * 2,
                      bf4[nq][0], bf4[nq][1], bf4[nq][2], bf4[nq][3]);
#pragma unroll
            for (int mi = 0; mi < 2; mi++)
#pragma unroll
                for (int ni = 0; ni < 8; ni++) {
                    if (HACC)
                        mma16816h(acch[mi][ni], af[mi][0], af[mi][1], af[mi][2], af[mi][3],
                                  bf4[ni >> 1][(ni & 1) * 2], bf4[ni >> 1][(ni & 1) * 2 + 1]);
                    else
                        mma16816f(accf[mi][ni], af[mi][0], af[mi][1], af[mi][2], af[mi][3],
                                  bf4[ni >> 1][(ni & 1) * 2], bf4[ni >> 1][(ni & 1) * 2 + 1]);
                }
        }
    }

    if (HACC) {
#pragma unroll
        for (int mi = 0; mi < 2; mi++)
#pragma unroll
            for (int ni = 0; ni < 8; ni++) {
                float2 lo = __half22float2(*(const __half2*)&acch[mi][ni][0]);
                float2 hi = __half22float2(*(const __half2*)&acch[mi][ni][1]);
                accf[mi][ni][0] = lo.x; accf[mi][ni][1] = lo.y;
                accf[mi][ni][2] = hi.x; accf[mi][ni][3] = hi.y;
            }
    }

    int g = lane >> 2, t = lane & 3;

    if (EPI == 0) {  // f16 direct + bias
        h16* C = (h16*)Cg;
#pragma unroll
        for (int mi = 0; mi < 2; mi++) {
            int r0 = wm * 32 + mi * 16 + g;
            float bv0 = bias ? bias[i0 + r0] : 0.f;
            float bv8 = bias ? bias[i0 + r0 + 8] : 0.f;
#pragma unroll
            for (int ni = 0; ni < 8; ni++) {
                int col = j0 + wn * 64 + ni * 8 + 2 * t;
                *(__half2*)&C[(size_t)(i0 + r0) * ldc + col] =
                    __floats2half2_rn(accf[mi][ni][0] + bv0, accf[mi][ni][1] + bv0);
                *(__half2*)&C[(size_t)(i0 + r0 + 8) * ldc + col] =
                    __floats2half2_rn(accf[mi][ni][2] + bv8, accf[mi][ni][3] + bv8);
            }
        }
    } else if (EPI == 4) {  // exp epilogue: f16 exp(acc*scale) + psum
        h16* C = (h16*)Cg;
        int slot = (j0 >> 7) * 2 + wn;
#pragma unroll
        for (int mi = 0; mi < 2; mi++) {
            int r0 = wm * 32 + mi * 16 + g;
            float s0 = 0.f, s8 = 0.f;
#pragma unroll
            for (int ni = 0; ni < 8; ni++) {
                int col = j0 + wn * 64 + ni * 8 + 2 * t;
                float p0 = __expf(accf[mi][ni][0] * scale);
                float p1 = __expf(accf[mi][ni][1] * scale);
                float p2 = __expf(accf[mi][ni][2] * scale);
                float p3 = __expf(accf[mi][ni][3] * scale);
                s0 += p0 + p1;
                s8 += p2 + p3;
                *(__half2*)&C[(size_t)(i0 + r0) * ldc + col]     = __floats2half2_rn(p0, p1);
                *(__half2*)&C[(size_t)(i0 + r0 + 8) * ldc + col] = __floats2half2_rn(p2, p3);
            }
            s0 += __shfl_xor_sync(0xffffffffu, s0, 1);
            s0 += __shfl_xor_sync(0xffffffffu, s0, 2);
            s8 += __shfl_xor_sync(0xffffffffu, s8, 1);
            s8 += __shfl_xor_sync(0xffffffffu, s8, 2);
            if (t == 0) {
                psum[(size_t)(i0 + r0) * 64 + slot]     = s0;
                psum[(size_t)(i0 + r0 + 8) * 64 + slot] = s8;
            }
        }
    } else if (EPI == 2 || EPI == 5) {  // f16 transposed via smem
        __syncthreads();
        h16* Ct = (h16*)sm;  // [j 128][i pitch 136]
#pragma unroll
        for (int mi = 0; mi < 2; mi++) {
            int r = wm * 32 + mi * 16 + g;
            float bv0 = (EPI == 2 && bias) ? bias[i0 + r] : 0.f;
            float bv8 = (EPI == 2 && bias) ? bias[i0 + r + 8] : 0.f;
#pragma unroll
            for (int ni = 0; ni < 8; ni++) {
                int c = wn * 64 + ni * 8 + 2 * t;
                float z0 = 1.f, z1 = 1.f;
                if (EPI == 5) {
                    z0 = zinv[j0 + c];
                    z1 = zinv[j0 + c + 1];
                }
                Ct[(size_t)c * 136 + r]           = __float2half(accf[mi][ni][0] * z0 + bv0);
                Ct[(size_t)(c + 1) * 136 + r]     = __float2half(accf[mi][ni][1] * z1 + bv0);
                Ct[(size_t)c * 136 + r + 8]       = __float2half(accf[mi][ni][2] * z0 + bv8);
                Ct[(size_t)(c + 1) * 136 + r + 8] = __float2half(accf[mi][ni][3] * z1 + bv8);
            }
        }
        __syncthreads();
        int j = tid >> 1, h = tid & 1;
        h16* Crow = (h16*)Cg + (size_t)(j0 + j) * ldc + i0 + h * 64;
        const h16* Srow = Ct + (size_t)j * 136 + h * 64;
#pragma unroll
        for (int q = 0; q < 8; q++)
            *(uint4*)(Crow + q * 8) = *(const uint4*)(Srow + q * 8);
    } else {  // EPI 3: fp32 + bias + residual
        float* C = (float*)Cg;
#pragma unroll
        for (int mi = 0; mi < 2; mi++) {
            int r0 = wm * 32 + mi * 16 + g;
            float bv0 = bias[i0 + r0];
            float bv8 = bias[i0 + r0 + 8];
#pragma unroll
            for (int ni = 0; ni < 8; ni++) {
                int col = j0 + wn * 64 + ni * 8 + 2 * t;
                size_t o0 = (size_t)(i0 + r0) * ldc + col;
                size_t o8 = (size_t)(i0 + r0 + 8) * ldc + col;
                float2 x0 = *(const float2*)&resid[o0];
                float2 x8 = *(const float2*)&resid[o8];
                *(float2*)&C[o0] = make_float2(accf[mi][ni][0] + bv0 + x0.x,
                                               accf[mi][ni][1] + bv0 + x0.y);
                *(float2*)&C[o8] = make_float2(accf[mi][ni][2] + bv8 + x8.x,
                                               accf[mi][ni][3] + bv8 + x8.y);
            }
        }
    }
}

// ---------------- GEMM wrappers (dynamic smem) ----------------
extern __shared__ unsigned char dyn_sm[];

__global__ __launch_bounds__(256, 2) void gemm_qkv_kernel(const float* __restrict__ bq,
                                                          const float* __restrict__ bk,
                                                          const float* __restrict__ bv) {
    int z = blockIdx.z, b = z / 3, m = z % 3;
    const h16* A = g_wb + (size_t)m * CC * CC;
    const h16* B = g_ht + (size_t)b * HWN * CC;
    int i0 = blockIdx.y * 128, j0 = blockIdx.x * 128;
    if (m == 0)
        gemm_core<2, 0>(dyn_sm, A, CC, B, CC, CC, g_qt + (size_t)b * HWN * CC, CC,
                        bq, 1.f, nullptr, nullptr, nullptr, i0, j0);
    else if (m == 1)
        gemm_core<2, 0>(dyn_sm, A, CC, B, CC, CC, g_kt + (size_t)b * HWN * CC, CC,
                        bk, 1.f, nullptr, nullptr, nullptr, i0, j0);
    else
        gemm_core<0, 0>(dyn_sm, A, CC, B, CC, CC, g_v + (size_t)b * CC * HWN, HWN,
                        bv, 1.f, nullptr, nullptr, nullptr, i0, j0);
}

__global__ __launch_bounds__(256, 3) void gemm_scores_kernel() {
    int b = blockIdx.z;
    int i0 = blockIdx.y * 128, j0 = blockIdx.x * 128;
    gemm_core<4, 1>(dyn_sm, g_qt + (size_t)b * HWN * CC, CC,
                    g_kt + (size_t)b * HWN * CC, CC, CC,
                    g_sb + (size_t)b * HWN * HWN, HWN, nullptr, QK_SCALE, nullptr,
                    g_psum + (size_t)b * HWN * 64, nullptr, i0, j0);
}

__global__ __launch_bounds__(256, 2) void gemm_av_kernel() {
    int b = blockIdx.z;
    int i0 = blockIdx.y * 128, j0 = blockIdx.x * 128;  // i over c, j over n
    gemm_core<5, 0>(dyn_sm, g_v + (size_t)b * CC * HWN, HWN,
                    g_sb + (size_t)b * HWN * HWN, HWN, HWN,
                    g_ot + (size_t)b * HWN * CC, CC, nullptr, 1.f, nullptr,
                    nullptr, g_zinv + (size_t)b * HWN, i0, j0);
}

__global__ __launch_bounds__(256, 2) void gemm_proj_kernel(const float* __restrict__ bp,
                                                           const float* __restrict__ x,
                                                           float* __restrict__ out) {
    int b = blockIdx.z;
    int i0 = blockIdx.y * 128, j0 = blockIdx.x * 128;  // i over o(c), j over n
    gemm_core<3, 0>(dyn_sm, g_wb + (size_t)3 * CC * CC, CC,
                    g_ot + (size_t)b * HWN * CC, CC, CC,
                    out + (size_t)b * CC * HWN, HWN, bp, 1.f, x + (size_t)b * CC * HWN,
                    nullptr, nullptr, i0, j0);
}

// ---------------- launch ----------------
extern "C" void kernel_launch(void* const* d_in, const int* in_sizes, int n_in,
                              void* d_out, int out_size) {
    const float* x     = (const float*)d_in[0];
    const float* gamma = (const float*)d_in[1];
    const float* beta  = (const float*)d_in[2];
    const float* wq = (const float*)d_in[3]; const float* bq = (const float*)d_in[4];
    const float* wk = (const float*)d_in[5]; const float* bk = (const float*)d_in[6];
    const float* wv = (const float*)d_in[7]; const float* bv = (const float*)d_in[8];
    const float* wp = (const float*)d_in[9]; const float* bp = (const float*)d_in[10];
    float* out = (float*)d_out;

    cudaFuncSetAttribute(gemm_qkv_kernel,    cudaFuncAttributeMaxDynamicSharedMemorySize, SMEM_TOTAL);
    cudaFuncSetAttribute(gemm_scores_kernel, cudaFuncAttributeMaxDynamicSharedMemorySize, SMEM_TOTAL);
    cudaFuncSetAttribute(gemm_av_kernel,     cudaFuncAttributeMaxDynamicSharedMemorySize, SMEM_TOTAL);
    cudaFuncSetAttribute(gemm_proj_kernel,   cudaFuncAttributeMaxDynamicSharedMemorySize, SMEM_TOTAL);

    wconv_kernel<<<dim3(CC * CC / 4 / 256, 4), 256>>>(wq, wk, wv, wp);
    gnt_kernel<<<BB * NG, 256>>>(x, gamma, beta);
    gemm_qkv_kernel<<<dim3(HWN / 128, CC / 128, BB * 3), 256, SMEM_TOTAL>>>(bq, bk, bv);
    gemm_scores_kernel<<<dim3(HWN / 128, HWN / 128, BB), 256, SMEM_TOTAL>>>();
    zred_kernel<<<BB * HWN / 256, 256>>>();
    gemm_av_kernel<<<dim3(HWN / 128, CC / 128, BB), 256, SMEM_TOTAL>>>();
    gemm_proj_kernel<<<dim3(HWN / 128, CC / 128, BB), 256, SMEM_TOTAL>>>(bp, x, out);
}

// round 14
// speedup vs baseline: 1.1970x; 1.0219x over previous
#include <cuda_runtime.h>
#include <cuda_fp16.h>
#include <cstdint>

typedef __half h16;

#define BB 4
#define CC 512
#define HWN 4096
#define NG 32
#define CPG 16
#define QK_SCALE 0.044194173824159216f  // 1/sqrt(512)
#define PAD 40                           // smem pitch (halves) for 32-wide K tiles
#define STAGES 3
#define OP_BYTES (128 * PAD * 2)         // one operand, one stage = 10240 B
#define STAGE_BYTES (2 * OP_BYTES)       // A + B per stage = 20480 B
#define SMEM_TOTAL (STAGES * STAGE_BYTES)  // 61440 B

// ---------------- static scratch ----------------
__device__ float g_stats[BB * NG * 2];          // mean, inv per (b, group)
__device__ h16   g_ht[(size_t)BB * HWN * CC];   // normed H^T [b][n][c]
__device__ h16   g_qt[(size_t)BB * HWN * CC];   // Q^T [b][n][c]
__device__ h16   g_kt[(size_t)BB * HWN * CC];   // K^T [b][m][c]
__device__ h16   g_v [(size_t)BB * CC * HWN];   // V   [b][c][m]
__device__ h16   g_sb[(size_t)BB * HWN * HWN];  // exp(scores) fp16 [b][n][m]
__device__ h16   g_ot[(size_t)BB * HWN * CC];   // (attn@V)^T [b][n][c]
__device__ h16   g_wb[(size_t)4 * CC * CC];     // wq,wk,wv,wp fp16
__device__ float g_psum[(size_t)BB * HWN * 64]; // partial row sums of exp(scores)
__device__ float g_zinv[(size_t)BB * HWN];      // 1 / rowsum

// ---------------- GroupNorm stats ----------------
__global__ __launch_bounds__(256) void gn_stats_kernel(const float* __restrict__ x) {
    int b = blockIdx.x / NG, g = blockIdx.x % NG;
    const float* xp = x + ((size_t)b * CC + (size_t)g * CPG) * HWN;
    const int n = CPG * HWN;  // 65536

    float s = 0.f, s2 = 0.f;
    for (int i = threadIdx.x * 4; i < n; i += 1024) {
        float4 v = *(const float4*)&xp[i];
        s  += v.x + v.y + v.z + v.w;
        s2 += v.x * v.x + v.y * v.y + v.z * v.z + v.w * v.w;
    }
    __shared__ float rs[256], rs2[256];
    rs[threadIdx.x] = s; rs2[threadIdx.x] = s2;
    __syncthreads();
    for (int st = 128; st > 0; st >>= 1) {
        if (threadIdx.x < st) {
            rs[threadIdx.x]  += rs[threadIdx.x + st];
            rs2[threadIdx.x] += rs2[threadIdx.x + st];
        }
        __syncthreads();
    }
    if (threadIdx.x == 0) {
        float mean = rs[0] / n;
        float var  = rs2[0] / n - mean * mean;
        g_stats[blockIdx.x * 2]     = mean;
        g_stats[blockIdx.x * 2 + 1] = rsqrtf(var + 1e-6f);
    }
}

// ---------------- norm + transpose: x [c][n] fp32 -> g_ht [n][c] fp16 ----------------
__global__ __launch_bounds__(256) void trn_kernel(const float* __restrict__ x,
                                                  const float* __restrict__ gamma,
                                                  const float* __restrict__ beta) {
    __shared__ float t[32][33];
    int b = blockIdx.z;
    int n0 = blockIdx.x * 32, c0 = blockIdx.y * 32;
    const float* src = x + (size_t)b * CC * HWN;
    h16* dst = g_ht + (size_t)b * HWN * CC;
    int tx = threadIdx.x & 31, ty = threadIdx.x >> 5;
#pragma unroll
    for (int r = 0; r < 4; r++) {
        int c = c0 + ty + r * 8;
        float mean = g_stats[(b * NG + c / CPG) * 2];
        float inv  = g_stats[(b * NG + c / CPG) * 2 + 1];
        float v = src[(size_t)c * HWN + n0 + tx];
        t[ty + r * 8][tx] = (v - mean) * inv * gamma[c] + beta[c];
    }
    __syncthreads();
#pragma unroll
    for (int r = 0; r < 4; r++)
        dst[(size_t)(n0 + ty + r * 8) * CC + c0 + tx] = __float2half(t[tx][ty + r * 8]);
}

// ---------------- weight fp32 -> fp16 ----------------
__global__ __launch_bounds__(256) void wconv_kernel(const float* __restrict__ wq,
                                                    const float* __restrict__ wk,
                                                    const float* __restrict__ wv,
                                                    const float* __restrict__ wp) {
    const float* srcs[4] = {wq, wk, wv, wp};
    int m = blockIdx.y;
    int idx = blockIdx.x * 256 + threadIdx.x;
    float4 v = *(const float4*)&srcs[m][idx * 4];
    h16* dst = g_wb + (size_t)m * CC * CC + idx * 4;
    *(__half2*)&dst[0] = __floats2half2_rn(v.x, v.y);
    *(__half2*)&dst[2] = __floats2half2_rn(v.z, v.w);
}

// ---------------- Z reduce: g_psum[row][64] -> g_zinv[row] ----------------
__global__ __launch_bounds__(256) void zred_kernel() {
    int row = blockIdx.x * 256 + threadIdx.x;
    const float* p = g_psum + (size_t)row * 64;
    float s = 0.f;
#pragma unroll
    for (int i = 0; i < 16; i++) {
        float4 v = *(const float4*)&p[i * 4];
        s += v.x + v.y + v.z + v.w;
    }
    g_zinv[row] = 1.0f / s;
}

// ---------------- mma helpers ----------------
__device__ __forceinline__ uint32_t smem_u32(const void* p) {
    return (uint32_t)__cvta_generic_to_shared(p);
}
__device__ __forceinline__ void cp16(uint32_t d, const void* s) {
    asm volatile("cp.async.cg.shared.global [%0], [%1], 16;" :: "r"(d), "l"(s));
}
__device__ __forceinline__ void ldmx4(uint32_t addr, uint32_t& r0, uint32_t& r1,
                                      uint32_t& r2, uint32_t& r3) {
    asm volatile("ldmatrix.sync.aligned.m8n8.x4.shared.b16 {%0,%1,%2,%3}, [%4];"
                 : "=r"(r0), "=r"(r1), "=r"(r2), "=r"(r3) : "r"(addr));
}
__device__ __forceinline__ void mma16816f(float c[4], uint32_t a0, uint32_t a1, uint32_t a2,
                                          uint32_t a3, uint32_t b0, uint32_t b1) {
    asm volatile(
        "mma.sync.aligned.m16n8k16.row.col.f32.f16.f16.f32 "
        "{%0,%1,%2,%3}, {%4,%5,%6,%7}, {%8,%9}, {%0,%1,%2,%3};"
        : "+f"(c[0]), "+f"(c[1]), "+f"(c[2]), "+f"(c[3])
        : "r"(a0), "r"(a1), "r"(a2), "r"(a3), "r"(b0), "r"(b1));
}
__device__ __forceinline__ void mma16816h(uint32_t c[2], uint32_t a0, uint32_t a1, uint32_t a2,
                                          uint32_t a3, uint32_t b0, uint32_t b1) {
    asm volatile(
        "mma.sync.aligned.m16n8k16.row.col.f16.f16.f16.f16 "
        "{%0,%1}, {%2,%3,%4,%5}, {%6,%7}, {%0,%1};"
        : "+r"(c[0]), "+r"(c[1])
        : "r"(a0), "r"(a1), "r"(a2), "r"(a3), "r"(b0), "r"(b1));
}

// ---------------- GEMM core: C[i 128][j 128] = sum_k A[i][k] B[j][k] ----------------
// 3-stage cp.async pipeline (R6/R10-validated shape). fp16 operands.
// HACC=1: fp16 accumulators.
// EPI 0: f16 direct, +bias   EPI 2: f16 transposed, +bias   EPI 3: fp32+bias+resid
// EPI 4: f16 exp(acc*scale) + psum   EPI 5: f16 transposed, col-scaled by zinv
template <int EPI, int HACC>
__device__ __forceinline__ void gemm_core(unsigned char* sm,
                                          const h16* __restrict__ A, int lda,
                                          const h16* __restrict__ B, int ldb, int K,
                                          void* Cg, int ldc,
                                          const float* __restrict__ bias, float scale,
                                          const float* __restrict__ resid,
                                          float* __restrict__ psum,
                                          const float* __restrict__ zinv,
                                          int i0, int j0) {
    int tid = threadIdx.x, lane = tid & 31, wid = tid >> 5;
    int wm = wid >> 1, wn = wid & 1;

    float    accf[2][8][4];
    uint32_t acch[2][8][2];
    if (HACC) {
#pragma unroll
        for (int mi = 0; mi < 2; mi++)
#pragma unroll
            for (int ni = 0; ni < 8; ni++) { acch[mi][ni][0] = 0u; acch[mi][ni][1] = 0u; }
    } else {
#pragma unroll
        for (int mi = 0; mi < 2; mi++)
#pragma unroll
            for (int ni = 0; ni < 8; ni++)
#pragma unroll
                for (int r = 0; r < 4; r++) accf[mi][ni][r] = 0.f;
    }

    int lr = tid >> 2, lc = (tid & 3) * 8;
    const h16* Ag  = A + (size_t)(i0 + lr) * lda + lc;
    const h16* Ag2 = Ag + (size_t)64 * lda;
    const h16* Bg  = B + (size_t)(j0 + lr) * ldb + lc;
    const h16* Bg2 = Bg + (size_t)64 * ldb;

    uint32_t smBase = smem_u32(sm);
    uint32_t wOff = smBase + (lr * PAD + lc) * 2;

    int am_row = wm * 32 + (lane & 15);
    int a_kh   = (lane >> 4) * 8;
    uint32_t aAddr = smBase + (am_row * PAD + a_kh) * 2;
    int b_nl  = (lane & 7) + ((lane >> 4) << 3);
    int b_sel = ((lane >> 3) & 1) * 8;
    uint32_t bAddr = smBase + OP_BYTES + ((wn * 64 + b_nl) * PAD + b_sel) * 2;

    const int nK = K / 32;

#pragma unroll
    for (int s = 0; s < STAGES - 1; s++) {
        uint32_t d = wOff + s * STAGE_BYTES;
        cp16(d,                           Ag  + s * 32);
        cp16(d + 64 * PAD * 2,            Ag2 + s * 32);
        cp16(d + OP_BYTES,                Bg  + s * 32);
        cp16(d + OP_BYTES + 64 * PAD * 2, Bg2 + s * 32);
        asm volatile("cp.async.commit_group;");
    }

    for (int kt = 0; kt < nK; kt++) {
        asm volatile("cp.async.wait_group 1;" ::: "memory");
        __syncthreads();

        int pf = kt + STAGES - 1;
        if (pf < nK) {
            uint32_t d = wOff + (pf % STAGES) * STAGE_BYTES;
            cp16(d,                           Ag  + pf * 32);
            cp16(d + 64 * PAD * 2,            Ag2 + pf * 32);
            cp16(d + OP_BYTES,                Bg  + pf * 32);
            cp16(d + OP_BYTES + 64 * PAD * 2, Bg2 + pf * 32);
        }
        asm volatile("cp.async.commit_group;");

        uint32_t stOff = (kt % STAGES) * STAGE_BYTES;
#pragma unroll
        for (int ks = 0; ks < 32; ks += 16) {
            uint32_t af[2][4];
#pragma unroll
            for (int mi = 0; mi < 2; mi++)
                ldmx4(aAddr + stOff + (mi * 16 * PAD + ks) * 2,
                      af[mi][0], af[mi][1], af[mi][2], af[mi][3]);
            uint32_t bf4[4][4];
#pragma unroll
            for (int nq = 0; nq < 4; nq++)
                ldmx4(bAddr + stOff + (nq * 16 * PAD + ks) * 2,
                      bf4[nq][0], bf4[nq][1], bf4[nq][2], bf4[nq][3]);
#pragma unroll
            for (int mi = 0; mi < 2; mi++)
#pragma unroll
                for (int ni = 0; ni < 8; ni++) {
                    if (HACC)
                        mma16816h(acch[mi][ni], af[mi][0], af[mi][1], af[mi][2], af[mi][3],
                                  bf4[ni >> 1][(ni & 1) * 2], bf4[ni >> 1][(ni & 1) * 2 + 1]);
                    else
                        mma16816f(accf[mi][ni], af[mi][0], af[mi][1], af[mi][2], af[mi][3],
                                  bf4[ni >> 1][(ni & 1) * 2], bf4[ni >> 1][(ni & 1) * 2 + 1]);
                }
        }
    }

    if (HACC) {
#pragma unroll
        for (int mi = 0; mi < 2; mi++)
#pragma unroll
            for (int ni = 0; ni < 8; ni++) {
                float2 lo = __half22float2(*(const __half2*)&acch[mi][ni][0]);
                float2 hi = __half22float2(*(const __half2*)&acch[mi][ni][1]);
                accf[mi][ni][0] = lo.x; accf[mi][ni][1] = lo.y;
                accf[mi][ni][2] = hi.x; accf[mi][ni][3] = hi.y;
            }
    }

    int g = lane >> 2, t = lane & 3;

    if (EPI == 0) {  // f16 direct + bias
        h16* C = (h16*)Cg;
#pragma unroll
        for (int mi = 0; mi < 2; mi++) {
            int r0 = wm * 32 + mi * 16 + g;
            float bv0 = bias ? bias[i0 + r0] : 0.f;
            float bv8 = bias ? bias[i0 + r0 + 8] : 0.f;
#pragma unroll
            for (int ni = 0; ni < 8; ni++) {
                int col = j0 + wn * 64 + ni * 8 + 2 * t;
                *(__half2*)&C[(size_t)(i0 + r0) * ldc + col] =
                    __floats2half2_rn(accf[mi][ni][0] + bv0, accf[mi][ni][1] + bv0);
                *(__half2*)&C[(size_t)(i0 + r0 + 8) * ldc + col] =
                    __floats2half2_rn(accf[mi][ni][2] + bv8, accf[mi][ni][3] + bv8);
            }
        }
    } else if (EPI == 4) {  // exp epilogue: f16 exp(acc*scale) + psum
        h16* C = (h16*)Cg;
        int slot = (j0 >> 7) * 2 + wn;
#pragma unroll
        for (int mi = 0; mi < 2; mi++) {
            int r0 = wm * 32 + mi * 16 + g;
            float s0 = 0.f, s8 = 0.f;
#pragma unroll
            for (int ni = 0; ni < 8; ni++) {
                int col = j0 + wn * 64 + ni * 8 + 2 * t;
                float p0 = __expf(accf[mi][ni][0] * scale);
                float p1 = __expf(accf[mi][ni][1] * scale);
                float p2 = __expf(accf[mi][ni][2] * scale);
                float p3 = __expf(accf[mi][ni][3] * scale);
                s0 += p0 + p1;
                s8 += p2 + p3;
                *(__half2*)&C[(size_t)(i0 + r0) * ldc + col]     = __floats2half2_rn(p0, p1);
                *(__half2*)&C[(size_t)(i0 + r0 + 8) * ldc + col] = __floats2half2_rn(p2, p3);
            }
            s0 += __shfl_xor_sync(0xffffffffu, s0, 1);
            s0 += __shfl_xor_sync(0xffffffffu, s0, 2);
            s8 += __shfl_xor_sync(0xffffffffu, s8, 1);
            s8 += __shfl_xor_sync(0xffffffffu, s8, 2);
            if (t == 0) {
                psum[(size_t)(i0 + r0) * 64 + slot]     = s0;
                psum[(size_t)(i0 + r0 + 8) * 64 + slot] = s8;
            }
        }
    } else if (EPI == 2 || EPI == 5) {  // f16 transposed via smem
        __syncthreads();
        h16* Ct = (h16*)sm;  // [j 128][i pitch 136]
#pragma unroll
        for (int mi = 0; mi < 2; mi++) {
            int r = wm * 32 + mi * 16 + g;
            float bv0 = (EPI == 2 && bias) ? bias[i0 + r] : 0.f;
            float bv8 = (EPI == 2 && bias) ? bias[i0 + r + 8] : 0.f;
#pragma unroll
            for (int ni = 0; ni < 8; ni++) {
                int c = wn * 64 + ni * 8 + 2 * t;
                float z0 = 1.f, z1 = 1.f;
                if (EPI == 5) {
                    z0 = zinv[j0 + c];
                    z1 = zinv[j0 + c + 1];
                }
                Ct[(size_t)c * 136 + r]           = __float2half(accf[mi][ni][0] * z0 + bv0);
                Ct[(size_t)(c + 1) * 136 + r]     = __float2half(accf[mi][ni][1] * z1 + bv0);
                Ct[(size_t)c * 136 + r + 8]       = __float2half(accf[mi][ni][2] * z0 + bv8);
                Ct[(size_t)(c + 1) * 136 + r + 8] = __float2half(accf[mi][ni][3] * z1 + bv8);
            }
        }
        __syncthreads();
        int j = tid >> 1, h = tid & 1;
        h16* Crow = (h16*)Cg + (size_t)(j0 + j) * ldc + i0 + h * 64;
        const h16* Srow = Ct + (size_t)j * 136 + h * 64;
#pragma unroll
        for (int q = 0; q < 8; q++)
            *(uint4*)(Crow + q * 8) = *(const uint4*)(Srow + q * 8);
    } else {  // EPI 3: fp32 + bias + residual
        float* C = (float*)Cg;
#pragma unroll
        for (int mi = 0; mi < 2; mi++) {
            int r0 = wm * 32 + mi * 16 + g;
            float bv0 = bias[i0 + r0];
            float bv8 = bias[i0 + r0 + 8];
#pragma unroll
            for (int ni = 0; ni < 8; ni++) {
                int col = j0 + wn * 64 + ni * 8 + 2 * t;
                size_t o0 = (size_t)(i0 + r0) * ldc + col;
                size_t o8 = (size_t)(i0 + r0 + 8) * ldc + col;
                float2 x0 = *(const float2*)&resid[o0];
                float2 x8 = *(const float2*)&resid[o8];
                *(float2*)&C[o0] = make_float2(accf[mi][ni][0] + bv0 + x0.x,
                                               accf[mi][ni][1] + bv0 + x0.y);
                *(float2*)&C[o8] = make_float2(accf[mi][ni][2] + bv8 + x8.x,
                                               accf[mi][ni][3] + bv8 + x8.y);
            }
        }
    }
}

// ---------------- GEMM wrappers (dynamic smem) ----------------
extern __shared__ unsigned char dyn_sm[];

__global__ __launch_bounds__(256, 3) void gemm_qkv_kernel(const float* __restrict__ bq,
                                                          const float* __restrict__ bk,
                                                          const float* __restrict__ bv) {
    int z = blockIdx.z, b = z / 3, m = z % 3;
    const h16* A = g_wb + (size_t)m * CC * CC;
    const h16* B = g_ht + (size_t)b * HWN * CC;
    int i0 = blockIdx.y * 128, j0 = blockIdx.x * 128;
    if (m == 0)
        gemm_core<2, 1>(dyn_sm, A, CC, B, CC, CC, g_qt + (size_t)b * HWN * CC, CC,
                        bq, 1.f, nullptr, nullptr, nullptr, i0, j0);
    else if (m == 1)
        gemm_core<2, 1>(dyn_sm, A, CC, B, CC, CC, g_kt + (size_t)b * HWN * CC, CC,
                        bk, 1.f, nullptr, nullptr, nullptr, i0, j0);
    else
        gemm_core<0, 1>(dyn_sm, A, CC, B, CC, CC, g_v + (size_t)b * CC * HWN, HWN,
                        bv, 1.f, nullptr, nullptr, nullptr, i0, j0);
}

__global__ __launch_bounds__(256, 3) void gemm_scores_kernel() {
    int b = blockIdx.z;
    int i0 = blockIdx.y * 128, j0 = blockIdx.x * 128;
    gemm_core<4, 1>(dyn_sm, g_qt + (size_t)b * HWN * CC, CC,
                    g_kt + (size_t)b * HWN * CC, CC, CC,
                    g_sb + (size_t)b * HWN * HWN, HWN, nullptr, QK_SCALE, nullptr,
                    g_psum + (size_t)b * HWN * 64, nullptr, i0, j0);
}

__global__ __launch_bounds__(256, 2) void gemm_av_kernel() {
    int b = blockIdx.z;
    int i0 = blockIdx.y * 128, j0 = blockIdx.x * 128;  // i over c, j over n
    gemm_core<5, 0>(dyn_sm, g_v + (size_t)b * CC * HWN, HWN,
                    g_sb + (size_t)b * HWN * HWN, HWN, HWN,
                    g_ot + (size_t)b * HWN * CC, CC, nullptr, 1.f, nullptr,
                    nullptr, g_zinv + (size_t)b * HWN, i0, j0);
}

__global__ __launch_bounds__(256, 2) void gemm_proj_kernel(const float* __restrict__ bp,
                                                           const float* __restrict__ x,
                                                           float* __restrict__ out) {
    int b = blockIdx.z;
    int i0 = blockIdx.y * 128, j0 = blockIdx.x * 128;  // i over o(c), j over n
    gemm_core<3, 0>(dyn_sm, g_wb + (size_t)3 * CC * CC, CC,
                    g_ot + (size_t)b * HWN * CC, CC, CC,
                    out + (size_t)b * CC * HWN, HWN, bp, 1.f, x + (size_t)b * CC * HWN,
                    nullptr, nullptr, i0, j0);
}

// ---------------- launch ----------------
extern "C" void kernel_launch(void* const* d_in, const int* in_sizes, int n_in,
                              void* d_out, int out_size) {
    const float* x     = (const float*)d_in[0];
    const float* gamma = (const float*)d_in[1];
    const float* beta  = (const float*)d_in[2];
    const float* wq = (const float*)d_in[3]; const float* bq = (const float*)d_in[4];
    const float* wk = (const float*)d_in[5]; const float* bk = (const float*)d_in[6];
    const float* wv = (const float*)d_in[7]; const float* bv = (const float*)d_in[8];
    const float* wp = (const float*)d_in[9]; const float* bp = (const float*)d_in[10];
    float* out = (float*)d_out;

    cudaFuncSetAttribute(gemm_qkv_kernel,    cudaFuncAttributeMaxDynamicSharedMemorySize, SMEM_TOTAL);
    cudaFuncSetAttribute(gemm_scores_kernel, cudaFuncAttributeMaxDynamicSharedMemorySize, SMEM_TOTAL);
    cudaFuncSetAttribute(gemm_av_kernel,     cudaFuncAttributeMaxDynamicSharedMemorySize, SMEM_TOTAL);
    cudaFuncSetAttribute(gemm_proj_kernel,   cudaFuncAttributeMaxDynamicSharedMemorySize, SMEM_TOTAL);

    gn_stats_kernel<<<BB * NG, 256>>>(x);
    trn_kernel<<<dim3(HWN / 32, CC / 32, BB), 256>>>(x, gamma, beta);
    wconv_kernel<<<dim3(CC * CC / 4 / 256, 4), 256>>>(wq, wk, wv, wp);
    gemm_qkv_kernel<<<dim3(HWN / 128, CC / 128, BB * 3), 256, SMEM_TOTAL>>>(bq, bk, bv);
    gemm_scores_kernel<<<dim3(HWN / 128, HWN / 128, BB), 256, SMEM_TOTAL>>>();
    zred_kernel<<<BB * HWN / 256, 256>>>();
    gemm_av_kernel<<<dim3(HWN / 128, CC / 128, BB), 256, SMEM_TOTAL>>>();
    gemm_proj_kernel<<<dim3(HWN / 128, CC / 128, BB), 256, SMEM_TOTAL>>>(bp, x, out);
}